// round 2
// baseline (speedup 1.0000x reference)
#include <cuda_runtime.h>
#include <math.h>

// Problem constants
#define BB   4
#define SEQ  2048
#define DD   1024
#define GG   256
#define QKD  128
#define HHID 2048
#define MROWS (BB*SEQ)        // 8192
#define NGRP  (MROWS/GG)      // 32
#define TWOH  (2*HHID)        // 4096

// -------- device scratch (no cudaMalloc allowed) --------
__device__ float g_normed[(size_t)MROWS*DD];        // 32 MB
__device__ float g_h[(size_t)MROWS*TWOH];           // 128 MB (v | gate, post-silu)
__device__ float g_qk[(size_t)MROWS*QKD];           // 4 MB
__device__ float g_qr[4][(size_t)MROWS*QKD];        // 16 MB (quad_q, lin_q, quad_k, lin_k)
__device__ float g_attn[(size_t)NGRP*GG*GG];        // 8 MB
__device__ float g_linkv[(size_t)BB*QKD*HHID];      // 4 MB
__device__ float g_gated[(size_t)MROWS*HHID];       // 64 MB
__device__ float g_sin[SEQ*64];
__device__ float g_cos[SEQ*64];

// ---------------- RoPE tables (bit-careful vs reference fp32 path) ----------
__global__ void rope_table_kernel() {
    int n = blockIdx.x, j = threadIdx.x;
    // inv_freq = 10000^(j/64) rounded to fp32 (matches correctly-rounded powf)
    float invf = (float)pow(10000.0, (double)j / 64.0);
    // reference computes the angle as an fp32 product, then sin/cos of that value
    float ang = (float)n * invf;
    g_sin[n*64 + j] = (float)sin((double)ang);
    g_cos[n*64 + j] = (float)cos((double)ang);
}

// ---------------- LayerNorm ----------------
__global__ void ln_kernel(const float* __restrict__ x,
                          const float* __restrict__ gam,
                          const float* __restrict__ bet) {
    int row = blockIdx.x, t = threadIdx.x;
    const float* xr = x + (size_t)row * DD;
    float v[4]; float s = 0.f;
#pragma unroll
    for (int c = 0; c < 4; c++) { v[c] = xr[t + 256*c]; s += v[c]; }
    __shared__ float red[8];
    __shared__ float bcast;
    int lane = t & 31, w = t >> 5;
#pragma unroll
    for (int o = 16; o; o >>= 1) s += __shfl_xor_sync(~0u, s, o);
    if (lane == 0) red[w] = s;
    __syncthreads();
    if (t == 0) { float tot = 0; for (int i = 0; i < 8; i++) tot += red[i]; bcast = tot / DD; }
    __syncthreads();
    float mu = bcast;
    float s2 = 0.f;
#pragma unroll
    for (int c = 0; c < 4; c++) { float d = v[c] - mu; s2 += d * d; }
#pragma unroll
    for (int o = 16; o; o >>= 1) s2 += __shfl_xor_sync(~0u, s2, o);
    __syncthreads();
    if (lane == 0) red[w] = s2;
    __syncthreads();
    if (t == 0) { float tot = 0; for (int i = 0; i < 8; i++) tot += red[i];
                  bcast = 1.0f / sqrtf(tot / DD + 1e-5f); }
    __syncthreads();
    float rstd = bcast;
    float* out = g_normed + (size_t)row * DD;
#pragma unroll
    for (int c = 0; c < 4; c++) {
        int d = t + 256*c;
        out[d] = (v[c] - mu) * rstd * gam[d] + bet[d];
    }
}

// ---------------- generic NN SGEMM (64x64 tile, 4x4/thread) ----------------
template<bool SILU, bool BIAS, bool RESID>
__global__ void sgemm_nn_kernel(const float* __restrict__ A, const float* __restrict__ B,
                                const float* __restrict__ bias, const float* __restrict__ resid,
                                float* __restrict__ C, int M, int N, int K) {
    __shared__ float As[16][64];
    __shared__ float Bs[16][64];
    const int tid = threadIdx.x;
    const int tx = tid & 15, ty = tid >> 4;
    const int row0 = blockIdx.y * 64, col0 = blockIdx.x * 64;
    const int ar = tid >> 2, ak = (tid & 3) << 2;
    const int br = tid >> 4, bc = (tid & 15) << 2;
    float acc[4][4] = {};
    const float* Ap = A + (size_t)(row0 + ar) * K + ak;
    const float* Bp = B + (size_t)br * N + col0 + bc;
    for (int k0 = 0; k0 < K; k0 += 16) {
        float4 a4 = *(const float4*)(Ap + k0);
        As[ak + 0][ar] = a4.x; As[ak + 1][ar] = a4.y;
        As[ak + 2][ar] = a4.z; As[ak + 3][ar] = a4.w;
        *(float4*)(&Bs[br][bc]) = *(const float4*)(Bp + (size_t)k0 * N);
        __syncthreads();
#pragma unroll
        for (int k = 0; k < 16; k++) {
            float4 av = *(float4*)(&As[k][ty << 2]);
            float4 bv = *(float4*)(&Bs[k][tx << 2]);
            float a_[4] = {av.x, av.y, av.z, av.w};
            float b_[4] = {bv.x, bv.y, bv.z, bv.w};
#pragma unroll
            for (int i = 0; i < 4; i++)
#pragma unroll
                for (int j = 0; j < 4; j++)
                    acc[i][j] = fmaf(a_[i], b_[j], acc[i][j]);
        }
        __syncthreads();
    }
#pragma unroll
    for (int i = 0; i < 4; i++) {
        int row = row0 + (ty << 2) + i;
#pragma unroll
        for (int j = 0; j < 4; j++) {
            int col = col0 + (tx << 2) + j;
            float c = acc[i][j];
            if (BIAS)  c += bias[col];
            if (SILU)  c = c / (1.0f + expf(-c));
            if (RESID) c += resid[(size_t)row * N + col];
            C[(size_t)row * N + col] = c;
        }
    }
}

// ---------------- OffsetScale + RoPE: qk -> 4 rotated heads ----------------
__global__ void rope_apply_kernel(const float* __restrict__ gamma,
                                  const float* __restrict__ beta) {
    int tid = threadIdx.x;
    int tok = blockIdx.x * 4 + (tid >> 6);
    int j   = tid & 63;
    int n   = tok & (SEQ - 1);
    float v1 = g_qk[(size_t)tok * QKD + j];
    float v2 = g_qk[(size_t)tok * QKD + j + 64];
    float sn = g_sin[n*64 + j], cs = g_cos[n*64 + j];
#pragma unroll
    for (int h = 0; h < 4; h++) {
        float a1 = v1 * gamma[h*QKD + j]      + beta[h*QKD + j];
        float a2 = v2 * gamma[h*QKD + j + 64] + beta[h*QKD + j + 64];
        g_qr[h][(size_t)tok * QKD + j]      = a1 * cs - a2 * sn;
        g_qr[h][(size_t)tok * QKD + j + 64] = a2 * cs + a1 * sn;
    }
}

// ---------------- group attention scores: attn = relu(qq.qk^T / g)^2 -------
__global__ void attn_sim_kernel() {
    int gid = blockIdx.z;
    int i0 = blockIdx.y * 64, j0 = blockIdx.x * 64;
    const float* Aq = g_qr[0] + (size_t)gid * GG * QKD;   // quad_q
    const float* Bk = g_qr[2] + (size_t)gid * GG * QKD;   // quad_k
    __shared__ float As[16][64];
    __shared__ float Bs[16][64];
    const int tid = threadIdx.x;
    const int tx = tid & 15, ty = tid >> 4;
    const int ar = tid >> 2, ak = (tid & 3) << 2;
    float acc[4][4] = {};
    for (int k0 = 0; k0 < QKD; k0 += 16) {
        float4 a4 = *(const float4*)(Aq + (size_t)(i0 + ar) * QKD + k0 + ak);
        As[ak+0][ar]=a4.x; As[ak+1][ar]=a4.y; As[ak+2][ar]=a4.z; As[ak+3][ar]=a4.w;
        float4 b4 = *(const float4*)(Bk + (size_t)(j0 + ar) * QKD + k0 + ak);
        Bs[ak+0][ar]=b4.x; Bs[ak+1][ar]=b4.y; Bs[ak+2][ar]=b4.z; Bs[ak+3][ar]=b4.w;
        __syncthreads();
#pragma unroll
        for (int k = 0; k < 16; k++) {
            float4 av = *(float4*)(&As[k][ty << 2]);
            float4 bv = *(float4*)(&Bs[k][tx << 2]);
            float a_[4] = {av.x, av.y, av.z, av.w};
            float b_[4] = {bv.x, bv.y, bv.z, bv.w};
#pragma unroll
            for (int i = 0; i < 4; i++)
#pragma unroll
                for (int j = 0; j < 4; j++)
                    acc[i][j] = fmaf(a_[i], b_[j], acc[i][j]);
        }
        __syncthreads();
    }
    float* Cp = g_attn + (size_t)gid * GG * GG;
#pragma unroll
    for (int i = 0; i < 4; i++)
#pragma unroll
        for (int j = 0; j < 4; j++) {
            float s = acc[i][j] * (1.0f / GG);
            s = fmaxf(s, 0.0f);
            Cp[(size_t)(i0 + (ty<<2) + i) * GG + j0 + (tx<<2) + j] = s * s;
        }
}

// ---------------- lin_kv[b,d,e] = sum_pos lin_k * v / SEQ  (TN GEMM) -------
__global__ void linkv_kernel() {
    int b  = blockIdx.z;
    int d0 = blockIdx.y * 64;
    int e0 = blockIdx.x * 64;
    const float* Kp = g_qr[3] + (size_t)b * SEQ * QKD;
    const float* Vp = g_h + (size_t)b * SEQ * TWOH;       // v = first H cols
    __shared__ float As[16][64];
    __shared__ float Bs[16][64];
    const int tid = threadIdx.x;
    const int tx = tid & 15, ty = tid >> 4;
    const int r = tid >> 4, c4 = (tid & 15) << 2;
    float acc[4][4] = {};
    for (int p0 = 0; p0 < SEQ; p0 += 16) {
        *(float4*)(&As[r][c4]) = *(const float4*)(Kp + (size_t)(p0 + r) * QKD + d0 + c4);
        *(float4*)(&Bs[r][c4]) = *(const float4*)(Vp + (size_t)(p0 + r) * TWOH + e0 + c4);
        __syncthreads();
#pragma unroll
        for (int k = 0; k < 16; k++) {
            float4 av = *(float4*)(&As[k][ty << 2]);
            float4 bv = *(float4*)(&Bs[k][tx << 2]);
            float a_[4] = {av.x, av.y, av.z, av.w};
            float b_[4] = {bv.x, bv.y, bv.z, bv.w};
#pragma unroll
            for (int i = 0; i < 4; i++)
#pragma unroll
                for (int j = 0; j < 4; j++)
                    acc[i][j] = fmaf(a_[i], b_[j], acc[i][j]);
        }
        __syncthreads();
    }
    float* Cp = g_linkv + (size_t)b * QKD * HHID;
#pragma unroll
    for (int i = 0; i < 4; i++)
#pragma unroll
        for (int j = 0; j < 4; j++)
            Cp[(size_t)(d0 + (ty<<2) + i) * HHID + e0 + (tx<<2) + j] =
                acc[i][j] * (1.0f / SEQ);
}

// ------- gated = gate * (attn@v + lin_q@lin_kv)  (fused two-phase GEMM) ----
__global__ void fused_out_kernel() {
    int e0 = blockIdx.x * 64;       // over H
    int p0 = blockIdx.y * 64;       // over rows
    int gid = p0 >> 8;
    int b   = p0 >> 11;
    int i0  = p0 & 255;
    __shared__ float As[16][64];
    __shared__ float Bs[16][64];
    const int tid = threadIdx.x;
    const int tx = tid & 15, ty = tid >> 4;
    const int ar = tid >> 2, ak = (tid & 3) << 2;
    const int r = tid >> 4, c4 = (tid & 15) << 2;
    float acc[4][4] = {};
    // phase 1: quadratic, K = 256 over group positions
    const float* attnP = g_attn + (size_t)gid * GG * GG;
    for (int k0 = 0; k0 < GG; k0 += 16) {
        float4 a4 = *(const float4*)(attnP + (size_t)(i0 + ar) * GG + k0 + ak);
        As[ak+0][ar]=a4.x; As[ak+1][ar]=a4.y; As[ak+2][ar]=a4.z; As[ak+3][ar]=a4.w;
        *(float4*)(&Bs[r][c4]) =
            *(const float4*)(g_h + (size_t)(gid * GG + k0 + r) * TWOH + e0 + c4);
        __syncthreads();
#pragma unroll
        for (int k = 0; k < 16; k++) {
            float4 av = *(float4*)(&As[k][ty << 2]);
            float4 bv = *(float4*)(&Bs[k][tx << 2]);
            float a_[4] = {av.x, av.y, av.z, av.w};
            float b_[4] = {bv.x, bv.y, bv.z, bv.w};
#pragma unroll
            for (int i = 0; i < 4; i++)
#pragma unroll
                for (int j = 0; j < 4; j++)
                    acc[i][j] = fmaf(a_[i], b_[j], acc[i][j]);
        }
        __syncthreads();
    }
    // phase 2: linear, K = 128 over qk dim
    const float* lq = g_qr[1];
    const float* kv = g_linkv + (size_t)b * QKD * HHID;
    for (int k0 = 0; k0 < QKD; k0 += 16) {
        float4 a4 = *(const float4*)(lq + (size_t)(p0 + ar) * QKD + k0 + ak);
        As[ak+0][ar]=a4.x; As[ak+1][ar]=a4.y; As[ak+2][ar]=a4.z; As[ak+3][ar]=a4.w;
        *(float4*)(&Bs[r][c4]) = *(const float4*)(kv + (size_t)(k0 + r) * HHID + e0 + c4);
        __syncthreads();
#pragma unroll
        for (int k = 0; k < 16; k++) {
            float4 av = *(float4*)(&As[k][ty << 2]);
            float4 bv = *(float4*)(&Bs[k][tx << 2]);
            float a_[4] = {av.x, av.y, av.z, av.w};
            float b_[4] = {bv.x, bv.y, bv.z, bv.w};
#pragma unroll
            for (int i = 0; i < 4; i++)
#pragma unroll
                for (int j = 0; j < 4; j++)
                    acc[i][j] = fmaf(a_[i], b_[j], acc[i][j]);
        }
        __syncthreads();
    }
#pragma unroll
    for (int i = 0; i < 4; i++) {
        int row = p0 + (ty << 2) + i;
#pragma unroll
        for (int j = 0; j < 4; j++) {
            int col = e0 + (tx << 2) + j;
            float gate = g_h[(size_t)row * TWOH + HHID + col];
            g_gated[(size_t)row * HHID + col] = gate * acc[i][j];
        }
    }
}

// ---------------------------------------------------------------------------
extern "C" void kernel_launch(void* const* d_in, const int* in_sizes, int n_in,
                              void* d_out, int out_size) {
    const float* x        = (const float*)d_in[0];
    const float* ln_g     = (const float*)d_in[1];
    const float* ln_b     = (const float*)d_in[2];
    const float* W_hidden = (const float*)d_in[3];
    const float* b_hidden = (const float*)d_in[4];
    const float* W_qk     = (const float*)d_in[5];
    const float* b_qk     = (const float*)d_in[6];
    const float* os_gamma = (const float*)d_in[7];
    const float* os_beta  = (const float*)d_in[8];
    const float* W_out    = (const float*)d_in[9];
    const float* b_out    = (const float*)d_in[10];
    float* out = (float*)d_out;

    float *normed, *h, *qk, *gated;
    cudaGetSymbolAddress((void**)&normed, g_normed);
    cudaGetSymbolAddress((void**)&h,      g_h);
    cudaGetSymbolAddress((void**)&qk,     g_qk);
    cudaGetSymbolAddress((void**)&gated,  g_gated);

    rope_table_kernel<<<SEQ, 64>>>();
    ln_kernel<<<MROWS, 256>>>(x, ln_g, ln_b);
    // h = silu(normed @ W_hidden + b_hidden)   [8192, 4096]
    sgemm_nn_kernel<true, true, false><<<dim3(TWOH/64, MROWS/64), 256>>>(
        normed, W_hidden, b_hidden, nullptr, h, MROWS, TWOH, DD);
    // qk = silu(normed @ W_qk + b_qk)          [8192, 128]
    sgemm_nn_kernel<true, true, false><<<dim3(QKD/64, MROWS/64), 256>>>(
        normed, W_qk, b_qk, nullptr, qk, MROWS, QKD, DD);
    rope_apply_kernel<<<MROWS/4, 256>>>(os_gamma, os_beta);
    attn_sim_kernel<<<dim3(GG/64, GG/64, NGRP), 256>>>();
    linkv_kernel<<<dim3(HHID/64, QKD/64, BB), 256>>>();
    fused_out_kernel<<<dim3(HHID/64, MROWS/64), 256>>>();
    // out = gated @ W_out + b_out + x          [8192, 1024]
    sgemm_nn_kernel<false, true, true><<<dim3(DD/64, MROWS/64), 256>>>(
        gated, W_out, b_out, x, out, MROWS, DD, HHID);
}

// round 7
// speedup vs baseline: 3.5028x; 3.5028x over previous
#include <cuda_runtime.h>
#include <cuda_bf16.h>
#include <math.h>
#include <cstdint>

// Problem constants
#define BB   4
#define SEQ  2048
#define DD   1024
#define GG   256
#define QKD  128
#define HHID 2048
#define MROWS (BB*SEQ)        // 8192
#define NGRP  (MROWS/GG)      // 32
#define TWOH  (2*HHID)        // 4096

// -------- device scratch (no cudaMalloc allowed) --------
__device__ __nv_bfloat16 g_normed_bf[(size_t)MROWS*DD];   // 16 MB
__device__ float g_h[(size_t)MROWS*TWOH];                 // 128 MB (v | gate)
__device__ float g_qk[(size_t)MROWS*QKD];                 // 4 MB
__device__ float g_qr[4][(size_t)MROWS*QKD];              // 16 MB
__device__ float g_attn[(size_t)NGRP*GG*GG];              // 8 MB
__device__ float g_linkv[(size_t)BB*QKD*HHID];            // 4 MB
__device__ __nv_bfloat16 g_gated_bf[(size_t)MROWS*HHID];  // 32 MB
__device__ __nv_bfloat16 g_whT[(size_t)TWOH*DD];          // 8 MB  W_hidden^T
__device__ __nv_bfloat16 g_wqkT[(size_t)QKD*DD];          // 0.25 MB
__device__ __nv_bfloat16 g_woT[(size_t)DD*HHID];          // 4 MB  W_out^T
__device__ float g_sin[SEQ*64];
__device__ float g_cos[SEQ*64];

// =================== PTX helpers (arch-portable: sm_80+ subset) ===================
__device__ __forceinline__ uint32_t smem_u32(const void* p) {
    uint32_t a;
    asm("{ .reg .u64 t; cvta.to.shared.u64 t, %1; cvt.u32.u64 %0, t; }" : "=r"(a) : "l"(p));
    return a;
}
#define SW128(o) ((o) ^ (((o) >> 3) & 0x70))

__device__ __forceinline__ void cpa16(uint32_t dst, const void* src) {
    asm volatile("cp.async.cg.shared.global [%0], [%1], 16;" :: "r"(dst), "l"(src));
}
#define CP_COMMIT() asm volatile("cp.async.commit_group;" ::: "memory")
#define CP_WAIT(n)  asm volatile("cp.async.wait_group %0;" :: "n"(n) : "memory")

__device__ __forceinline__ void ldsm_x4(uint32_t* r, uint32_t addr) {
    asm volatile("ldmatrix.sync.aligned.m8n8.x4.shared.b16 {%0,%1,%2,%3}, [%4];"
                 : "=r"(r[0]), "=r"(r[1]), "=r"(r[2]), "=r"(r[3]) : "r"(addr));
}
__device__ __forceinline__ void ldsm_x2(uint32_t* r, uint32_t addr) {
    asm volatile("ldmatrix.sync.aligned.m8n8.x2.shared.b16 {%0,%1}, [%2];"
                 : "=r"(r[0]), "=r"(r[1]) : "r"(addr));
}
__device__ __forceinline__ void mma_16816(float* c, const uint32_t* a, const uint32_t* b) {
    asm volatile(
        "mma.sync.aligned.m16n8k16.row.col.f32.bf16.bf16.f32 "
        "{%0,%1,%2,%3}, {%4,%5,%6,%7}, {%8,%9}, {%0,%1,%2,%3};"
        : "+f"(c[0]), "+f"(c[1]), "+f"(c[2]), "+f"(c[3])
        : "r"(a[0]), "r"(a[1]), "r"(a[2]), "r"(a[3]), "r"(b[0]), "r"(b[1]));
}

// ====== bf16 tensor-core GEMM: C[M,N] = A[M,K] @ Bt[N,K]^T  (128x128 CTA tile) ======
// A, Bt bf16 row-major (K contiguous). 8 warps (2x4), warp tile 64x32, mma m16n8k16.
template<int K_TOT, bool SILU_, bool RESID_>
__global__ void __launch_bounds__(256)
mm_bf16_kernel(const __nv_bfloat16* __restrict__ A,
               const __nv_bfloat16* __restrict__ Bt,
               const float* __restrict__ bias,
               const float* __restrict__ resid,
               float* __restrict__ C, int ldC)
{
    constexpr int STAGES   = K_TOT / 64;    // 64 bf16 (128B) per K stage
    constexpr int TILE_B   = 128 * 128;     // 16 KB per tile buffer
    extern __shared__ char smem[];
    const uint32_t aB = smem_u32(smem);
    const uint32_t bB = aB + 2 * TILE_B;

    const int tid = threadIdx.x, wid = tid >> 5, lane = tid & 31;
    const int m0 = blockIdx.y * 128, n0 = blockIdx.x * 128;
    const int wm = (wid >> 2) * 64;         // warp row offset (0/64)
    const int wn = (wid & 3) * 32;          // warp col offset (0..96)

    // ---- stage loaders: 1024 x 16B chunks each, 4 per thread ----
    auto loadA = [&](int s, int buf) {
        uint32_t base = aB + buf * TILE_B;
        const __nv_bfloat16* src = A + (size_t)m0 * K_TOT + s * 64;
#pragma unroll
        for (int i = 0; i < 4; i++) {
            int c = tid + i * 256;
            int row = c >> 3, col = c & 7;
            cpa16(base + SW128(row * 128 + col * 16),
                  src + (size_t)row * K_TOT + col * 8);
        }
    };
    auto loadB = [&](int s, int buf) {
        uint32_t base = bB + buf * TILE_B;
        const __nv_bfloat16* src = Bt + (size_t)n0 * K_TOT + s * 64;
#pragma unroll
        for (int i = 0; i < 4; i++) {
            int c = tid + i * 256;
            int row = c >> 3, col = c & 7;
            cpa16(base + SW128(row * 128 + col * 16),
                  src + (size_t)row * K_TOT + col * 8);
        }
    };

    float acc[4][4][4] = {};   // [mi][ni][reg]

    // precomputed per-lane ldmatrix offsets (within a tile buffer, k-step 0)
    const int a_row = wm + (lane & 15);
    const int a_kof = (lane >> 4) * 8;           // 0 or 8
    const int b_row = wn + (lane & 7);
    const int b_kof = ((lane >> 3) & 1) * 8;     // 0 or 8 (lanes 16+ harmless)

    loadA(0, 0); loadB(0, 0); CP_COMMIT();

    for (int s = 0; s < STAGES; s++) {
        if (s + 1 < STAGES) {
            loadA(s + 1, (s + 1) & 1); loadB(s + 1, (s + 1) & 1);
            CP_COMMIT();
            CP_WAIT(1);
        } else {
            CP_WAIT(0);
        }
        __syncthreads();
        const uint32_t abase = aB + (s & 1) * TILE_B;
        const uint32_t bbase = bB + (s & 1) * TILE_B;
#pragma unroll
        for (int ks = 0; ks < 4; ks++) {
            uint32_t af[4][4];
#pragma unroll
            for (int mi = 0; mi < 4; mi++) {
                int row = a_row + mi * 16;
                int k = ks * 16 + a_kof;
                ldsm_x4(af[mi], abase + SW128(row * 128 + k * 2));
            }
            uint32_t bf[4][2];
#pragma unroll
            for (int ni = 0; ni < 4; ni++) {
                int row = b_row + ni * 8;
                int k = ks * 16 + b_kof;
                ldsm_x2(bf[ni], bbase + SW128(row * 128 + k * 2));
            }
#pragma unroll
            for (int mi = 0; mi < 4; mi++)
#pragma unroll
                for (int ni = 0; ni < 4; ni++)
                    mma_16816(acc[mi][ni], af[mi], bf[ni]);
        }
        __syncthreads();
    }

    // ---- epilogue ----
    const int er = m0 + wm + (lane >> 2);
    const int ec = n0 + wn + (lane & 3) * 2;
#pragma unroll
    for (int mi = 0; mi < 4; mi++) {
#pragma unroll
        for (int ni = 0; ni < 4; ni++) {
            int col = ec + ni * 8;
#pragma unroll
            for (int half = 0; half < 2; half++) {
                int row = er + mi * 16 + half * 8;
                float v0 = acc[mi][ni][half * 2 + 0] + bias[col + 0];
                float v1 = acc[mi][ni][half * 2 + 1] + bias[col + 1];
                if (SILU_) {
                    v0 = v0 / (1.0f + expf(-v0));
                    v1 = v1 / (1.0f + expf(-v1));
                }
                if (RESID_) {
                    v0 += resid[(size_t)row * ldC + col + 0];
                    v1 += resid[(size_t)row * ldC + col + 1];
                }
                float2 o; o.x = v0; o.y = v1;
                *(float2*)(C + (size_t)row * ldC + col) = o;
            }
        }
    }
}

// =================== transpose + fp32->bf16 convert ==========
__global__ void transpose_bf_kernel(const float* __restrict__ in,
                                    __nv_bfloat16* __restrict__ out, int R, int Cc) {
    __shared__ float t[32][33];
    int c0 = blockIdx.x * 32, r0 = blockIdx.y * 32;
    int x = threadIdx.x, y = threadIdx.y;   // 32 x 8
#pragma unroll
    for (int i = 0; i < 32; i += 8)
        t[y + i][x] = in[(size_t)(r0 + y + i) * Cc + c0 + x];
    __syncthreads();
#pragma unroll
    for (int i = 0; i < 32; i += 8)
        out[(size_t)(c0 + y + i) * R + r0 + x] = __float2bfloat16(t[x][y + i]);
}

// ---------------- RoPE tables ----------------
__global__ void rope_table_kernel() {
    int n = blockIdx.x, j = threadIdx.x;
    float invf = (float)pow(10000.0, (double)j / 64.0);
    float ang = (float)n * invf;
    g_sin[n*64 + j] = (float)sin((double)ang);
    g_cos[n*64 + j] = (float)cos((double)ang);
}

// ---------------- LayerNorm (emits bf16 A operand) ----------------
__global__ void ln_kernel(const float* __restrict__ x,
                          const float* __restrict__ gam,
                          const float* __restrict__ bet) {
    int row = blockIdx.x, t = threadIdx.x;
    const float* xr = x + (size_t)row * DD;
    float v[4]; float s = 0.f;
#pragma unroll
    for (int c = 0; c < 4; c++) { v[c] = xr[t + 256*c]; s += v[c]; }
    __shared__ float red[8];
    __shared__ float bcast;
    int lane = t & 31, w = t >> 5;
#pragma unroll
    for (int o = 16; o; o >>= 1) s += __shfl_xor_sync(~0u, s, o);
    if (lane == 0) red[w] = s;
    __syncthreads();
    if (t == 0) { float tot = 0; for (int i = 0; i < 8; i++) tot += red[i]; bcast = tot / DD; }
    __syncthreads();
    float mu = bcast;
    float s2 = 0.f;
#pragma unroll
    for (int c = 0; c < 4; c++) { float d = v[c] - mu; s2 += d * d; }
#pragma unroll
    for (int o = 16; o; o >>= 1) s2 += __shfl_xor_sync(~0u, s2, o);
    __syncthreads();
    if (lane == 0) red[w] = s2;
    __syncthreads();
    if (t == 0) { float tot = 0; for (int i = 0; i < 8; i++) tot += red[i];
                  bcast = 1.0f / sqrtf(tot / DD + 1e-5f); }
    __syncthreads();
    float rstd = bcast;
    __nv_bfloat16* out = g_normed_bf + (size_t)row * DD;
#pragma unroll
    for (int c = 0; c < 4; c++) {
        int d = t + 256*c;
        out[d] = __float2bfloat16((v[c] - mu) * rstd * gam[d] + bet[d]);
    }
}

// ---------------- OffsetScale + RoPE ----------------
__global__ void rope_apply_kernel(const float* __restrict__ gamma,
                                  const float* __restrict__ beta) {
    int tid = threadIdx.x;
    int tok = blockIdx.x * 4 + (tid >> 6);
    int j   = tid & 63;
    int n   = tok & (SEQ - 1);
    float v1 = g_qk[(size_t)tok * QKD + j];
    float v2 = g_qk[(size_t)tok * QKD + j + 64];
    float sn = g_sin[n*64 + j], cs = g_cos[n*64 + j];
#pragma unroll
    for (int h = 0; h < 4; h++) {
        float a1 = v1 * gamma[h*QKD + j]      + beta[h*QKD + j];
        float a2 = v2 * gamma[h*QKD + j + 64] + beta[h*QKD + j + 64];
        g_qr[h][(size_t)tok * QKD + j]      = a1 * cs - a2 * sn;
        g_qr[h][(size_t)tok * QKD + j + 64] = a2 * cs + a1 * sn;
    }
}

// ---------------- group attention scores: attn = relu(q.k^T / g)^2 -------
__global__ void attn_sim_kernel() {
    int gid = blockIdx.z;
    int i0 = blockIdx.y * 64, j0 = blockIdx.x * 64;
    const float* Aq = g_qr[0] + (size_t)gid * GG * QKD;
    const float* Bk = g_qr[2] + (size_t)gid * GG * QKD;
    __shared__ float As[16][64];
    __shared__ float Bs[16][64];
    const int tid = threadIdx.x;
    const int tx = tid & 15, ty = tid >> 4;
    const int ar = tid >> 2, ak = (tid & 3) << 2;
    float acc[4][4] = {};
    for (int k0 = 0; k0 < QKD; k0 += 16) {
        float4 a4 = *(const float4*)(Aq + (size_t)(i0 + ar) * QKD + k0 + ak);
        As[ak+0][ar]=a4.x; As[ak+1][ar]=a4.y; As[ak+2][ar]=a4.z; As[ak+3][ar]=a4.w;
        float4 b4 = *(const float4*)(Bk + (size_t)(j0 + ar) * QKD + k0 + ak);
        Bs[ak+0][ar]=b4.x; Bs[ak+1][ar]=b4.y; Bs[ak+2][ar]=b4.z; Bs[ak+3][ar]=b4.w;
        __syncthreads();
#pragma unroll
        for (int k = 0; k < 16; k++) {
            float4 av = *(float4*)(&As[k][ty << 2]);
            float4 bv = *(float4*)(&Bs[k][tx << 2]);
            float a_[4] = {av.x, av.y, av.z, av.w};
            float b_[4] = {bv.x, bv.y, bv.z, bv.w};
#pragma unroll
            for (int i = 0; i < 4; i++)
#pragma unroll
                for (int j = 0; j < 4; j++)
                    acc[i][j] = fmaf(a_[i], b_[j], acc[i][j]);
        }
        __syncthreads();
    }
    float* Cp = g_attn + (size_t)gid * GG * GG;
#pragma unroll
    for (int i = 0; i < 4; i++)
#pragma unroll
        for (int j = 0; j < 4; j++) {
            float s = acc[i][j] * (1.0f / GG);
            s = fmaxf(s, 0.0f);
            Cp[(size_t)(i0 + (ty<<2) + i) * GG + j0 + (tx<<2) + j] = s * s;
        }
}

// ---------------- lin_kv[b,d,e] = sum_pos lin_k * v / SEQ ----------------
__global__ void linkv_kernel() {
    int b  = blockIdx.z;
    int d0 = blockIdx.y * 64;
    int e0 = blockIdx.x * 64;
    const float* Kp = g_qr[3] + (size_t)b * SEQ * QKD;
    const float* Vp = g_h + (size_t)b * SEQ * TWOH;
    __shared__ float As[16][64];
    __shared__ float Bs[16][64];
    const int tid = threadIdx.x;
    const int tx = tid & 15, ty = tid >> 4;
    const int r = tid >> 4, c4 = (tid & 15) << 2;
    float acc[4][4] = {};
    for (int p0 = 0; p0 < SEQ; p0 += 16) {
        *(float4*)(&As[r][c4]) = *(const float4*)(Kp + (size_t)(p0 + r) * QKD + d0 + c4);
        *(float4*)(&Bs[r][c4]) = *(const float4*)(Vp + (size_t)(p0 + r) * TWOH + e0 + c4);
        __syncthreads();
#pragma unroll
        for (int k = 0; k < 16; k++) {
            float4 av = *(float4*)(&As[k][ty << 2]);
            float4 bv = *(float4*)(&Bs[k][tx << 2]);
            float a_[4] = {av.x, av.y, av.z, av.w};
            float b_[4] = {bv.x, bv.y, bv.z, bv.w};
#pragma unroll
            for (int i = 0; i < 4; i++)
#pragma unroll
                for (int j = 0; j < 4; j++)
                    acc[i][j] = fmaf(a_[i], b_[j], acc[i][j]);
        }
        __syncthreads();
    }
    float* Cp = g_linkv + (size_t)b * QKD * HHID;
#pragma unroll
    for (int i = 0; i < 4; i++)
#pragma unroll
        for (int j = 0; j < 4; j++)
            Cp[(size_t)(d0 + (ty<<2) + i) * HHID + e0 + (tx<<2) + j] =
                acc[i][j] * (1.0f / SEQ);
}

// ------- gated = gate * (attn@v + lin_q@lin_kv)  -> bf16 A operand ---------
__global__ void fused_out_kernel() {
    int e0 = blockIdx.x * 64;
    int p0 = blockIdx.y * 64;
    int gid = p0 >> 8;
    int b   = p0 >> 11;
    int i0  = p0 & 255;
    __shared__ float As[16][64];
    __shared__ float Bs[16][64];
    const int tid = threadIdx.x;
    const int tx = tid & 15, ty = tid >> 4;
    const int ar = tid >> 2, ak = (tid & 3) << 2;
    const int r = tid >> 4, c4 = (tid & 15) << 2;
    float acc[4][4] = {};
    const float* attnP = g_attn + (size_t)gid * GG * GG;
    for (int k0 = 0; k0 < GG; k0 += 16) {
        float4 a4 = *(const float4*)(attnP + (size_t)(i0 + ar) * GG + k0 + ak);
        As[ak+0][ar]=a4.x; As[ak+1][ar]=a4.y; As[ak+2][ar]=a4.z; As[ak+3][ar]=a4.w;
        *(float4*)(&Bs[r][c4]) =
            *(const float4*)(g_h + (size_t)(gid * GG + k0 + r) * TWOH + e0 + c4);
        __syncthreads();
#pragma unroll
        for (int k = 0; k < 16; k++) {
            float4 av = *(float4*)(&As[k][ty << 2]);
            float4 bv = *(float4*)(&Bs[k][tx << 2]);
            float a_[4] = {av.x, av.y, av.z, av.w};
            float b_[4] = {bv.x, bv.y, bv.z, bv.w};
#pragma unroll
            for (int i = 0; i < 4; i++)
#pragma unroll
                for (int j = 0; j < 4; j++)
                    acc[i][j] = fmaf(a_[i], b_[j], acc[i][j]);
        }
        __syncthreads();
    }
    const float* lq = g_qr[1];
    const float* kv = g_linkv + (size_t)b * QKD * HHID;
    for (int k0 = 0; k0 < QKD; k0 += 16) {
        float4 a4 = *(const float4*)(lq + (size_t)(p0 + ar) * QKD + k0 + ak);
        As[ak+0][ar]=a4.x; As[ak+1][ar]=a4.y; As[ak+2][ar]=a4.z; As[ak+3][ar]=a4.w;
        *(float4*)(&Bs[r][c4]) = *(const float4*)(kv + (size_t)(k0 + r) * HHID + e0 + c4);
        __syncthreads();
#pragma unroll
        for (int k = 0; k < 16; k++) {
            float4 av = *(float4*)(&As[k][ty << 2]);
            float4 bv = *(float4*)(&Bs[k][tx << 2]);
            float a_[4] = {av.x, av.y, av.z, av.w};
            float b_[4] = {bv.x, bv.y, bv.z, bv.w};
#pragma unroll
            for (int i = 0; i < 4; i++)
#pragma unroll
                for (int j = 0; j < 4; j++)
                    acc[i][j] = fmaf(a_[i], b_[j], acc[i][j]);
        }
        __syncthreads();
    }
#pragma unroll
    for (int i = 0; i < 4; i++) {
        int row = p0 + (ty << 2) + i;
#pragma unroll
        for (int j = 0; j < 4; j++) {
            int col = e0 + (tx << 2) + j;
            float gate = g_h[(size_t)row * TWOH + HHID + col];
            g_gated_bf[(size_t)row * HHID + col] = __float2bfloat16(gate * acc[i][j]);
        }
    }
}

// ---------------------------------------------------------------------------
extern "C" void kernel_launch(void* const* d_in, const int* in_sizes, int n_in,
                              void* d_out, int out_size) {
    const float* x        = (const float*)d_in[0];
    const float* ln_g     = (const float*)d_in[1];
    const float* ln_b     = (const float*)d_in[2];
    const float* W_hidden = (const float*)d_in[3];
    const float* b_hidden = (const float*)d_in[4];
    const float* W_qk     = (const float*)d_in[5];
    const float* b_qk     = (const float*)d_in[6];
    const float* os_gamma = (const float*)d_in[7];
    const float* os_beta  = (const float*)d_in[8];
    const float* W_out    = (const float*)d_in[9];
    const float* b_out    = (const float*)d_in[10];
    float* out = (float*)d_out;

    __nv_bfloat16 *normed_bf, *whT, *wqkT, *woT, *gated_bf;
    float *h, *qk;
    cudaGetSymbolAddress((void**)&normed_bf, g_normed_bf);
    cudaGetSymbolAddress((void**)&whT,  g_whT);
    cudaGetSymbolAddress((void**)&wqkT, g_wqkT);
    cudaGetSymbolAddress((void**)&woT,  g_woT);
    cudaGetSymbolAddress((void**)&gated_bf, g_gated_bf);
    cudaGetSymbolAddress((void**)&h,  g_h);
    cudaGetSymbolAddress((void**)&qk, g_qk);

    const int SMEM_MM = 4 * 128 * 128;   // 64 KB (2-stage A + B tiles)
    cudaFuncSetAttribute(mm_bf16_kernel<1024,true,false>,
                         cudaFuncAttributeMaxDynamicSharedMemorySize, SMEM_MM);
    cudaFuncSetAttribute(mm_bf16_kernel<2048,false,true>,
                         cudaFuncAttributeMaxDynamicSharedMemorySize, SMEM_MM);

    // weight transposes (+bf16 convert)
    transpose_bf_kernel<<<dim3(TWOH/32, DD/32), dim3(32,8)>>>(W_hidden, whT, DD, TWOH);
    transpose_bf_kernel<<<dim3(QKD/32,  DD/32), dim3(32,8)>>>(W_qk,  wqkT, DD, QKD);
    transpose_bf_kernel<<<dim3(DD/32, HHID/32), dim3(32,8)>>>(W_out, woT,  HHID, DD);

    rope_table_kernel<<<SEQ, 64>>>();
    ln_kernel<<<MROWS, 256>>>(x, ln_g, ln_b);

    // h = silu(normed @ W_hidden + b)   [8192, 4096]  (HMMA bf16)
    mm_bf16_kernel<1024,true,false><<<dim3(TWOH/128, MROWS/128), 256, SMEM_MM>>>(
        normed_bf, whT, b_hidden, nullptr, h, TWOH);
    // qk = silu(normed @ W_qk + b)      [8192, 128]   (HMMA bf16)
    mm_bf16_kernel<1024,true,false><<<dim3(QKD/128, MROWS/128), 256, SMEM_MM>>>(
        normed_bf, wqkT, b_qk, nullptr, qk, QKD);

    rope_apply_kernel<<<MROWS/4, 256>>>(os_gamma, os_beta);
    attn_sim_kernel<<<dim3(GG/64, GG/64, NGRP), 256>>>();
    linkv_kernel<<<dim3(HHID/64, QKD/64, BB), 256>>>();
    fused_out_kernel<<<dim3(HHID/64, MROWS/64), 256>>>();

    // out = gated @ W_out + b_out + x   [8192, 1024]  (HMMA bf16)
    mm_bf16_kernel<2048,false,true><<<dim3(DD/128, MROWS/128), 256, SMEM_MM>>>(
        gated_bf, woT, b_out, x, out, DD);
}

// round 8
// speedup vs baseline: 5.7329x; 1.6367x over previous
#include <cuda_runtime.h>
#include <cuda_bf16.h>
#include <math.h>
#include <cstdint>

// Problem constants
#define BB   4
#define SEQ  2048
#define DD   1024
#define GG   256
#define QKD  128
#define HHID 2048
#define MROWS (BB*SEQ)        // 8192
#define NGRP  (MROWS/GG)      // 32
#define TWOH  (2*HHID)        // 4096

// -------- device scratch (no cudaMalloc allowed) --------
__device__ __nv_bfloat16 g_normed_bf[(size_t)MROWS*DD];    // 16 MB
__device__ __nv_bfloat16 g_h_bf[(size_t)MROWS*TWOH];       // 64 MB (v | gate)
__device__ float g_qk[(size_t)MROWS*QKD];                  // 4 MB
__device__ float g_qr[2][(size_t)MROWS*QKD];               // 8 MB (quad_q, quad_k)
__device__ __nv_bfloat16 g_linq_bf[(size_t)MROWS*QKD];     // 2 MB
__device__ __nv_bfloat16 g_linkT_bf[(size_t)BB*QKD*SEQ];   // 2 MB  lin_k^T per batch [d][n]
__device__ __nv_bfloat16 g_attn_bf[(size_t)NGRP*GG*GG];    // 4 MB
__device__ __nv_bfloat16 g_linkv_bf[(size_t)BB*QKD*HHID];  // 2 MB
__device__ __nv_bfloat16 g_gated_bf[(size_t)MROWS*HHID];   // 32 MB
__device__ __nv_bfloat16 g_whT[(size_t)TWOH*DD];           // 8 MB
__device__ __nv_bfloat16 g_wqkT[(size_t)QKD*DD];           // 0.25 MB
__device__ __nv_bfloat16 g_woT[(size_t)DD*HHID];           // 4 MB
__device__ float g_sin[SEQ*64];
__device__ float g_cos[SEQ*64];

// =================== PTX helpers (arch-portable: sm_80+ subset) ===================
__device__ __forceinline__ uint32_t smem_u32(const void* p) {
    uint32_t a;
    asm("{ .reg .u64 t; cvta.to.shared.u64 t, %1; cvt.u32.u64 %0, t; }" : "=r"(a) : "l"(p));
    return a;
}
#define SW128(o) ((o) ^ (((o) >> 3) & 0x70))   // 128B rows
#define SWZ256(o) ((o) ^ (((o) >> 4) & 0x70))  // 256B rows

__device__ __forceinline__ void cpa16(uint32_t dst, const void* src) {
    asm volatile("cp.async.cg.shared.global [%0], [%1], 16;" :: "r"(dst), "l"(src));
}
#define CP_COMMIT() asm volatile("cp.async.commit_group;" ::: "memory")
#define CP_WAIT(n)  asm volatile("cp.async.wait_group %0;" :: "n"(n) : "memory")

__device__ __forceinline__ void ldsm_x4(uint32_t* r, uint32_t addr) {
    asm volatile("ldmatrix.sync.aligned.m8n8.x4.shared.b16 {%0,%1,%2,%3}, [%4];"
                 : "=r"(r[0]), "=r"(r[1]), "=r"(r[2]), "=r"(r[3]) : "r"(addr));
}
__device__ __forceinline__ void ldsm_x2(uint32_t* r, uint32_t addr) {
    asm volatile("ldmatrix.sync.aligned.m8n8.x2.shared.b16 {%0,%1}, [%2];"
                 : "=r"(r[0]), "=r"(r[1]) : "r"(addr));
}
__device__ __forceinline__ void ldsm_x4t(uint32_t* r, uint32_t addr) {
    asm volatile("ldmatrix.sync.aligned.m8n8.x4.trans.shared.b16 {%0,%1,%2,%3}, [%4];"
                 : "=r"(r[0]), "=r"(r[1]), "=r"(r[2]), "=r"(r[3]) : "r"(addr));
}
__device__ __forceinline__ void mma_16816(float* c, const uint32_t* a, const uint32_t* b) {
    asm volatile(
        "mma.sync.aligned.m16n8k16.row.col.f32.bf16.bf16.f32 "
        "{%0,%1,%2,%3}, {%4,%5,%6,%7}, {%8,%9}, {%0,%1,%2,%3};"
        : "+f"(c[0]), "+f"(c[1]), "+f"(c[2]), "+f"(c[3])
        : "r"(a[0]), "r"(a[1]), "r"(a[2]), "r"(a[3]), "r"(b[0]), "r"(b[1]));
}
__device__ __forceinline__ void st_bf2(__nv_bfloat16* p, float a, float b) {
    *(__nv_bfloat162*)p = __floats2bfloat162_rn(a, b);
}

// ====== bf16 tensor-core GEMM: C[M,N] = A[M,K] @ Bt[N,K]^T  (128x128 CTA tile) ======
template<int K_TOT, bool SILU_, bool RESID_, bool OUTBF_>
__global__ void __launch_bounds__(256)
mm_bf16_kernel(const __nv_bfloat16* __restrict__ A,
               const __nv_bfloat16* __restrict__ Bt,
               const float* __restrict__ bias,
               const float* __restrict__ resid,
               float* __restrict__ Cf, __nv_bfloat16* __restrict__ Cb, int ldC)
{
    constexpr int STAGES   = K_TOT / 64;
    constexpr int TILE_B   = 128 * 128;     // 16 KB
    extern __shared__ char smem[];
    const uint32_t aB = smem_u32(smem);
    const uint32_t bB = aB + 2 * TILE_B;

    const int tid = threadIdx.x, wid = tid >> 5, lane = tid & 31;
    const int m0 = blockIdx.y * 128, n0 = blockIdx.x * 128;
    const int wm = (wid >> 2) * 64;
    const int wn = (wid & 3) * 32;

    auto loadA = [&](int s, int buf) {
        uint32_t base = aB + buf * TILE_B;
        const __nv_bfloat16* src = A + (size_t)m0 * K_TOT + s * 64;
#pragma unroll
        for (int i = 0; i < 4; i++) {
            int c = tid + i * 256;
            int row = c >> 3, col = c & 7;
            cpa16(base + SW128(row * 128 + col * 16), src + (size_t)row * K_TOT + col * 8);
        }
    };
    auto loadB = [&](int s, int buf) {
        uint32_t base = bB + buf * TILE_B;
        const __nv_bfloat16* src = Bt + (size_t)n0 * K_TOT + s * 64;
#pragma unroll
        for (int i = 0; i < 4; i++) {
            int c = tid + i * 256;
            int row = c >> 3, col = c & 7;
            cpa16(base + SW128(row * 128 + col * 16), src + (size_t)row * K_TOT + col * 8);
        }
    };

    float acc[4][4][4] = {};
    const int a_row = wm + (lane & 15);
    const int a_kof = (lane >> 4) * 8;
    const int b_row = wn + (lane & 7);
    const int b_kof = ((lane >> 3) & 1) * 8;

    loadA(0, 0); loadB(0, 0); CP_COMMIT();

    for (int s = 0; s < STAGES; s++) {
        if (s + 1 < STAGES) {
            loadA(s + 1, (s + 1) & 1); loadB(s + 1, (s + 1) & 1);
            CP_COMMIT(); CP_WAIT(1);
        } else CP_WAIT(0);
        __syncthreads();
        const uint32_t abase = aB + (s & 1) * TILE_B;
        const uint32_t bbase = bB + (s & 1) * TILE_B;
#pragma unroll
        for (int ks = 0; ks < 4; ks++) {
            uint32_t af[4][4];
#pragma unroll
            for (int mi = 0; mi < 4; mi++)
                ldsm_x4(af[mi], abase + SW128((a_row + mi * 16) * 128 + (ks * 16 + a_kof) * 2));
            uint32_t bf[4][2];
#pragma unroll
            for (int ni = 0; ni < 4; ni++)
                ldsm_x2(bf[ni], bbase + SW128((b_row + ni * 8) * 128 + (ks * 16 + b_kof) * 2));
#pragma unroll
            for (int mi = 0; mi < 4; mi++)
#pragma unroll
                for (int ni = 0; ni < 4; ni++)
                    mma_16816(acc[mi][ni], af[mi], bf[ni]);
        }
        __syncthreads();
    }

    const int er = m0 + wm + (lane >> 2);
    const int ec = n0 + wn + (lane & 3) * 2;
#pragma unroll
    for (int mi = 0; mi < 4; mi++)
#pragma unroll
        for (int ni = 0; ni < 4; ni++) {
            int col = ec + ni * 8;
#pragma unroll
            for (int half = 0; half < 2; half++) {
                int row = er + mi * 16 + half * 8;
                float v0 = acc[mi][ni][half * 2 + 0] + bias[col + 0];
                float v1 = acc[mi][ni][half * 2 + 1] + bias[col + 1];
                if (SILU_) { v0 = v0 / (1.0f + expf(-v0)); v1 = v1 / (1.0f + expf(-v1)); }
                if (RESID_) {
                    v0 += resid[(size_t)row * ldC + col + 0];
                    v1 += resid[(size_t)row * ldC + col + 1];
                }
                if (OUTBF_) st_bf2(Cb + (size_t)row * ldC + col, v0, v1);
                else { float2 o; o.x = v0; o.y = v1; *(float2*)(Cf + (size_t)row * ldC + col) = o; }
            }
        }
}

// ====== linkv HMMA: linkv[b,d,e] = sum_n lin_kT[b,d,n] * v[b,n,e] / SEQ ======
// CTA: 128 d x 64 e.  Warps 4x2 (warp tile 32x32).  A normal, B via ldmatrix.trans.
__global__ void __launch_bounds__(256)
linkv_hmma_kernel()
{
    constexpr int A_B = 128 * 128;   // 16 KB
    constexpr int B_B = 64 * 128;    // 8 KB
    extern __shared__ char smem[];
    const uint32_t aB = smem_u32(smem);
    const uint32_t bB = aB + 2 * A_B;

    const int tid = threadIdx.x, wid = tid >> 5, lane = tid & 31;
    const int b  = blockIdx.y;
    const int e0 = blockIdx.x * 64;
    const int wm = (wid & 3) * 32;
    const int wn = (wid >> 2) * 32;

    auto loadA = [&](int s, int buf) {
        uint32_t base = aB + buf * A_B;
        const __nv_bfloat16* src = g_linkT_bf + (size_t)b * QKD * SEQ + s * 64;
#pragma unroll
        for (int i = 0; i < 4; i++) {
            int c = tid + i * 256;
            int row = c >> 3, col = c & 7;
            cpa16(base + SW128(row * 128 + col * 16), src + (size_t)row * SEQ + col * 8);
        }
    };
    auto loadB = [&](int s, int buf) {
        uint32_t base = bB + buf * B_B;
        const __nv_bfloat16* src = g_h_bf + ((size_t)(b * SEQ + s * 64)) * TWOH + e0;
#pragma unroll
        for (int i = 0; i < 2; i++) {
            int c = tid + i * 256;
            int row = c >> 3, col = c & 7;
            cpa16(base + SW128(row * 128 + col * 16), src + (size_t)row * TWOH + col * 8);
        }
    };

    float acc[2][4][4] = {};
    const int a_row = wm + (lane & 15);
    const int a_kof = (lane >> 4) * 8;
    const int bt_k  = lane & 15;                 // k row within 16-chunk
    const int bt_n  = ((lane >> 4) & 1) * 8;     // n sub-offset

    loadA(0, 0); loadB(0, 0); CP_COMMIT();
    for (int s = 0; s < SEQ / 64; s++) {
        if (s + 1 < SEQ / 64) {
            loadA(s + 1, (s + 1) & 1); loadB(s + 1, (s + 1) & 1);
            CP_COMMIT(); CP_WAIT(1);
        } else CP_WAIT(0);
        __syncthreads();
        const uint32_t abase = aB + (s & 1) * A_B;
        const uint32_t bbase = bB + (s & 1) * B_B;
#pragma unroll
        for (int ks = 0; ks < 4; ks++) {
            uint32_t af[2][4];
#pragma unroll
            for (int mi = 0; mi < 2; mi++)
                ldsm_x4(af[mi], abase + SW128((a_row + mi * 16) * 128 + (ks * 16 + a_kof) * 2));
            uint32_t bt[2][4];
#pragma unroll
            for (int g = 0; g < 2; g++)
                ldsm_x4t(bt[g], bbase + SW128((ks * 16 + bt_k) * 128 + (wn + g * 16 + bt_n) * 2));
#pragma unroll
            for (int mi = 0; mi < 2; mi++)
#pragma unroll
                for (int g = 0; g < 2; g++) {
                    mma_16816(acc[mi][g * 2 + 0], af[mi], &bt[g][0]);
                    mma_16816(acc[mi][g * 2 + 1], af[mi], &bt[g][2]);
                }
        }
        __syncthreads();
    }

    __nv_bfloat16* Cp = g_linkv_bf + (size_t)b * QKD * HHID;
    const int er = wm + (lane >> 2);
    const int ec = e0 + wn + (lane & 3) * 2;
#pragma unroll
    for (int mi = 0; mi < 2; mi++)
#pragma unroll
        for (int ni = 0; ni < 4; ni++) {
            int col = ec + ni * 8;
#pragma unroll
            for (int half = 0; half < 2; half++) {
                int row = er + mi * 16 + half * 8;
                st_bf2(Cp + (size_t)row * HHID + col,
                       acc[mi][ni][half * 2 + 0] * (1.0f / SEQ),
                       acc[mi][ni][half * 2 + 1] * (1.0f / SEQ));
            }
        }
}

// ====== fused HMMA: gated = gate * (attn@v + lin_q@lin_kv)  (128p x 128e tile) ======
__global__ void __launch_bounds__(256)
fused_hmma_kernel()
{
    constexpr int TILE_B = 128 * 128;   // 16 KB each (A: 128x64, B: 64x128 @256B rows)
    extern __shared__ char smem[];
    const uint32_t aB = smem_u32(smem);
    const uint32_t bB = aB + 2 * TILE_B;

    const int tid = threadIdx.x, wid = tid >> 5, lane = tid & 31;
    const int p0 = blockIdx.y * 128, e0 = blockIdx.x * 128;
    const int gid = p0 >> 8, b = p0 >> 11, i0 = p0 & 255;
    const int wm = (wid >> 2) * 64;
    const int wn = (wid & 3) * 32;

    auto loadStage = [&](int s, int buf) {
        uint32_t abase = aB + buf * TILE_B;
        uint32_t bbase = bB + buf * TILE_B;
        if (s < 4) {   // phase 1: attn @ v, K = 256 (j)
            const __nv_bfloat16* asrc = g_attn_bf + (size_t)gid * GG * GG + (size_t)i0 * GG + s * 64;
#pragma unroll
            for (int i = 0; i < 4; i++) {
                int c = tid + i * 256;
                int row = c >> 3, col = c & 7;
                cpa16(abase + SW128(row * 128 + col * 16), asrc + (size_t)row * GG + col * 8);
            }
            const __nv_bfloat16* bsrc = g_h_bf + ((size_t)(gid * GG + s * 64)) * TWOH + e0;
#pragma unroll
            for (int i = 0; i < 4; i++) {
                int c = tid + i * 256;
                int row = c >> 4, col = c & 15;
                cpa16(bbase + SWZ256(row * 256 + col * 16), bsrc + (size_t)row * TWOH + col * 8);
            }
        } else {       // phase 2: lin_q @ lin_kv, K = 128 (d)
            int s2 = s - 4;
            const __nv_bfloat16* asrc = g_linq_bf + (size_t)p0 * QKD + s2 * 64;
#pragma unroll
            for (int i = 0; i < 4; i++) {
                int c = tid + i * 256;
                int row = c >> 3, col = c & 7;
                cpa16(abase + SW128(row * 128 + col * 16), asrc + (size_t)row * QKD + col * 8);
            }
            const __nv_bfloat16* bsrc = g_linkv_bf + (size_t)b * QKD * HHID + (size_t)(s2 * 64) * HHID + e0;
#pragma unroll
            for (int i = 0; i < 4; i++) {
                int c = tid + i * 256;
                int row = c >> 4, col = c & 15;
                cpa16(bbase + SWZ256(row * 256 + col * 16), bsrc + (size_t)row * TWOH / 2 + col * 8);
            }
        }
    };

    float acc[4][4][4] = {};
    const int a_row = wm + (lane & 15);
    const int a_kof = (lane >> 4) * 8;
    const int bt_k  = lane & 15;
    const int bt_n  = ((lane >> 4) & 1) * 8;

    loadStage(0, 0); CP_COMMIT();
    for (int s = 0; s < 6; s++) {
        if (s + 1 < 6) { loadStage(s + 1, (s + 1) & 1); CP_COMMIT(); CP_WAIT(1); }
        else CP_WAIT(0);
        __syncthreads();
        const uint32_t abase = aB + (s & 1) * TILE_B;
        const uint32_t bbase = bB + (s & 1) * TILE_B;
#pragma unroll
        for (int ks = 0; ks < 4; ks++) {
            uint32_t af[4][4];
#pragma unroll
            for (int mi = 0; mi < 4; mi++)
                ldsm_x4(af[mi], abase + SW128((a_row + mi * 16) * 128 + (ks * 16 + a_kof) * 2));
            uint32_t bt[2][4];
#pragma unroll
            for (int g = 0; g < 2; g++)
                ldsm_x4t(bt[g], bbase + SWZ256((ks * 16 + bt_k) * 256 + (wn + g * 16 + bt_n) * 2));
#pragma unroll
            for (int mi = 0; mi < 4; mi++)
#pragma unroll
                for (int g = 0; g < 2; g++) {
                    mma_16816(acc[mi][g * 2 + 0], af[mi], &bt[g][0]);
                    mma_16816(acc[mi][g * 2 + 1], af[mi], &bt[g][2]);
                }
        }
        __syncthreads();
    }

    const int er = p0 + wm + (lane >> 2);
    const int ec = e0 + wn + (lane & 3) * 2;
#pragma unroll
    for (int mi = 0; mi < 4; mi++)
#pragma unroll
        for (int ni = 0; ni < 4; ni++) {
            int col = ec + ni * 8;
#pragma unroll
            for (int half = 0; half < 2; half++) {
                int row = er + mi * 16 + half * 8;
                float g0 = __bfloat162float(g_h_bf[(size_t)row * TWOH + HHID + col + 0]);
                float g1 = __bfloat162float(g_h_bf[(size_t)row * TWOH + HHID + col + 1]);
                st_bf2(g_gated_bf + (size_t)row * HHID + col,
                       g0 * acc[mi][ni][half * 2 + 0], g1 * acc[mi][ni][half * 2 + 1]);
            }
        }
}

// =================== transpose + fp32->bf16 convert ==========
__global__ void transpose_bf_kernel(const float* __restrict__ in,
                                    __nv_bfloat16* __restrict__ out, int R, int Cc) {
    __shared__ float t[32][33];
    int c0 = blockIdx.x * 32, r0 = blockIdx.y * 32;
    int x = threadIdx.x, y = threadIdx.y;
#pragma unroll
    for (int i = 0; i < 32; i += 8)
        t[y + i][x] = in[(size_t)(r0 + y + i) * Cc + c0 + x];
    __syncthreads();
#pragma unroll
    for (int i = 0; i < 32; i += 8)
        out[(size_t)(c0 + y + i) * R + r0 + x] = __float2bfloat16(t[x][y + i]);
}

// ---------------- RoPE tables (fp32 sin/cos, 2-ulp full-range reduction) ----------
__global__ void rope_table_kernel() {
    int n = blockIdx.x, j = threadIdx.x;
    float invf = (float)pow(10000.0, (double)j / 64.0);
    float ang = (float)n * invf;
    g_sin[n*64 + j] = sinf(ang);
    g_cos[n*64 + j] = cosf(ang);
}

// ---------------- LayerNorm (emits bf16 A operand) ----------------
__global__ void ln_kernel(const float* __restrict__ x,
                          const float* __restrict__ gam,
                          const float* __restrict__ bet) {
    int row = blockIdx.x, t = threadIdx.x;
    const float* xr = x + (size_t)row * DD;
    float v[4]; float s = 0.f;
#pragma unroll
    for (int c = 0; c < 4; c++) { v[c] = xr[t + 256*c]; s += v[c]; }
    __shared__ float red[8];
    __shared__ float bcast;
    int lane = t & 31, w = t >> 5;
#pragma unroll
    for (int o = 16; o; o >>= 1) s += __shfl_xor_sync(~0u, s, o);
    if (lane == 0) red[w] = s;
    __syncthreads();
    if (t == 0) { float tot = 0; for (int i = 0; i < 8; i++) tot += red[i]; bcast = tot / DD; }
    __syncthreads();
    float mu = bcast;
    float s2 = 0.f;
#pragma unroll
    for (int c = 0; c < 4; c++) { float d = v[c] - mu; s2 += d * d; }
#pragma unroll
    for (int o = 16; o; o >>= 1) s2 += __shfl_xor_sync(~0u, s2, o);
    __syncthreads();
    if (lane == 0) red[w] = s2;
    __syncthreads();
    if (t == 0) { float tot = 0; for (int i = 0; i < 8; i++) tot += red[i];
                  bcast = 1.0f / sqrtf(tot / DD + 1e-5f); }
    __syncthreads();
    float rstd = bcast;
    __nv_bfloat16* out = g_normed_bf + (size_t)row * DD;
#pragma unroll
    for (int c = 0; c < 4; c++) {
        int d = t + 256*c;
        out[d] = __float2bfloat16((v[c] - mu) * rstd * gam[d] + bet[d]);
    }
}

// -------- OffsetScale + RoPE: quad fp32, lin_q bf16, lin_k transposed bf16 --------
__global__ void rope_apply_kernel(const float* __restrict__ gamma,
                                  const float* __restrict__ beta) {
    int tid = threadIdx.x;
    int tok = blockIdx.x * 4 + (tid >> 6);
    int j   = tid & 63;
    int n   = tok & (SEQ - 1);
    int b   = tok >> 11;
    float v1 = g_qk[(size_t)tok * QKD + j];
    float v2 = g_qk[(size_t)tok * QKD + j + 64];
    float sn = g_sin[n*64 + j], cs = g_cos[n*64 + j];
    // h=0: quad_q -> g_qr[0] fp32
    {
        float a1 = v1 * gamma[0*QKD + j]      + beta[0*QKD + j];
        float a2 = v2 * gamma[0*QKD + j + 64] + beta[0*QKD + j + 64];
        g_qr[0][(size_t)tok * QKD + j]      = a1 * cs - a2 * sn;
        g_qr[0][(size_t)tok * QKD + j + 64] = a2 * cs + a1 * sn;
    }
    // h=2: quad_k -> g_qr[1] fp32
    {
        float a1 = v1 * gamma[2*QKD + j]      + beta[2*QKD + j];
        float a2 = v2 * gamma[2*QKD + j + 64] + beta[2*QKD + j + 64];
        g_qr[1][(size_t)tok * QKD + j]      = a1 * cs - a2 * sn;
        g_qr[1][(size_t)tok * QKD + j + 64] = a2 * cs + a1 * sn;
    }
    // h=1: lin_q -> bf16 [tok][d]
    {
        float a1 = v1 * gamma[1*QKD + j]      + beta[1*QKD + j];
        float a2 = v2 * gamma[1*QKD + j + 64] + beta[1*QKD + j + 64];
        g_linq_bf[(size_t)tok * QKD + j]      = __float2bfloat16(a1 * cs - a2 * sn);
        g_linq_bf[(size_t)tok * QKD + j + 64] = __float2bfloat16(a2 * cs + a1 * sn);
    }
    // h=3: lin_k -> bf16 transposed [b][d][n]
    {
        float a1 = v1 * gamma[3*QKD + j]      + beta[3*QKD + j];
        float a2 = v2 * gamma[3*QKD + j + 64] + beta[3*QKD + j + 64];
        __nv_bfloat16* base = g_linkT_bf + (size_t)b * QKD * SEQ;
        base[(size_t)j * SEQ + n]        = __float2bfloat16(a1 * cs - a2 * sn);
        base[(size_t)(j + 64) * SEQ + n] = __float2bfloat16(a2 * cs + a1 * sn);
    }
}

// ---------------- group attention scores: attn = relu(q.k^T / g)^2 -> bf16 -------
__global__ void attn_sim_kernel() {
    int gid = blockIdx.z;
    int i0 = blockIdx.y * 64, j0 = blockIdx.x * 64;
    const float* Aq = g_qr[0] + (size_t)gid * GG * QKD;
    const float* Bk = g_qr[1] + (size_t)gid * GG * QKD;
    __shared__ float As[16][64];
    __shared__ float Bs[16][64];
    const int tid = threadIdx.x;
    const int tx = tid & 15, ty = tid >> 4;
    const int ar = tid >> 2, ak = (tid & 3) << 2;
    float acc[4][4] = {};
    for (int k0 = 0; k0 < QKD; k0 += 16) {
        float4 a4 = *(const float4*)(Aq + (size_t)(i0 + ar) * QKD + k0 + ak);
        As[ak+0][ar]=a4.x; As[ak+1][ar]=a4.y; As[ak+2][ar]=a4.z; As[ak+3][ar]=a4.w;
        float4 b4 = *(const float4*)(Bk + (size_t)(j0 + ar) * QKD + k0 + ak);
        Bs[ak+0][ar]=b4.x; Bs[ak+1][ar]=b4.y; Bs[ak+2][ar]=b4.z; Bs[ak+3][ar]=b4.w;
        __syncthreads();
#pragma unroll
        for (int k = 0; k < 16; k++) {
            float4 av = *(float4*)(&As[k][ty << 2]);
            float4 bv = *(float4*)(&Bs[k][tx << 2]);
            float a_[4] = {av.x, av.y, av.z, av.w};
            float b_[4] = {bv.x, bv.y, bv.z, bv.w};
#pragma unroll
            for (int i = 0; i < 4; i++)
#pragma unroll
                for (int j = 0; j < 4; j++)
                    acc[i][j] = fmaf(a_[i], b_[j], acc[i][j]);
        }
        __syncthreads();
    }
    __nv_bfloat16* Cp = g_attn_bf + (size_t)gid * GG * GG;
#pragma unroll
    for (int i = 0; i < 4; i++) {
        int row = i0 + (ty<<2) + i;
        int col = j0 + (tx<<2);
        float r[4];
#pragma unroll
        for (int j = 0; j < 4; j++) {
            float s = fmaxf(acc[i][j] * (1.0f / GG), 0.0f);
            r[j] = s * s;
        }
        st_bf2(Cp + (size_t)row * GG + col,     r[0], r[1]);
        st_bf2(Cp + (size_t)row * GG + col + 2, r[2], r[3]);
    }
}

// ---------------------------------------------------------------------------
extern "C" void kernel_launch(void* const* d_in, const int* in_sizes, int n_in,
                              void* d_out, int out_size) {
    const float* x        = (const float*)d_in[0];
    const float* ln_g     = (const float*)d_in[1];
    const float* ln_b     = (const float*)d_in[2];
    const float* W_hidden = (const float*)d_in[3];
    const float* b_hidden = (const float*)d_in[4];
    const float* W_qk     = (const float*)d_in[5];
    const float* b_qk     = (const float*)d_in[6];
    const float* os_gamma = (const float*)d_in[7];
    const float* os_beta  = (const float*)d_in[8];
    const float* W_out    = (const float*)d_in[9];
    const float* b_out    = (const float*)d_in[10];
    float* out = (float*)d_out;

    __nv_bfloat16 *normed_bf, *whT, *wqkT, *woT, *gated_bf, *h_bf;
    float *qk;
    cudaGetSymbolAddress((void**)&normed_bf, g_normed_bf);
    cudaGetSymbolAddress((void**)&whT,  g_whT);
    cudaGetSymbolAddress((void**)&wqkT, g_wqkT);
    cudaGetSymbolAddress((void**)&woT,  g_woT);
    cudaGetSymbolAddress((void**)&gated_bf, g_gated_bf);
    cudaGetSymbolAddress((void**)&h_bf, g_h_bf);
    cudaGetSymbolAddress((void**)&qk, g_qk);

    const int SMEM_MM = 4 * 128 * 128;   // 64 KB
    const int SMEM_LK = 2 * 16384 + 2 * 8192;  // 48 KB
    cudaFuncSetAttribute(mm_bf16_kernel<1024,true,false,true>,
                         cudaFuncAttributeMaxDynamicSharedMemorySize, SMEM_MM);
    cudaFuncSetAttribute(mm_bf16_kernel<1024,true,false,false>,
                         cudaFuncAttributeMaxDynamicSharedMemorySize, SMEM_MM);
    cudaFuncSetAttribute(mm_bf16_kernel<2048,false,true,false>,
                         cudaFuncAttributeMaxDynamicSharedMemorySize, SMEM_MM);
    cudaFuncSetAttribute(linkv_hmma_kernel,
                         cudaFuncAttributeMaxDynamicSharedMemorySize, SMEM_LK);
    cudaFuncSetAttribute(fused_hmma_kernel,
                         cudaFuncAttributeMaxDynamicSharedMemorySize, SMEM_MM);

    transpose_bf_kernel<<<dim3(TWOH/32, DD/32), dim3(32,8)>>>(W_hidden, whT, DD, TWOH);
    transpose_bf_kernel<<<dim3(QKD/32,  DD/32), dim3(32,8)>>>(W_qk,  wqkT, DD, QKD);
    transpose_bf_kernel<<<dim3(DD/32, HHID/32), dim3(32,8)>>>(W_out, woT,  HHID, DD);

    rope_table_kernel<<<SEQ, 64>>>();
    ln_kernel<<<MROWS, 256>>>(x, ln_g, ln_b);

    // h = silu(normed @ W_hidden + b) -> bf16 [8192, 4096]
    mm_bf16_kernel<1024,true,false,true><<<dim3(TWOH/128, MROWS/128), 256, SMEM_MM>>>(
        normed_bf, whT, b_hidden, nullptr, nullptr, h_bf, TWOH);
    // qk = silu(normed @ W_qk + b) -> fp32 [8192, 128]
    mm_bf16_kernel<1024,true,false,false><<<dim3(QKD/128, MROWS/128), 256, SMEM_MM>>>(
        normed_bf, wqkT, b_qk, nullptr, qk, nullptr, QKD);

    rope_apply_kernel<<<MROWS/4, 256>>>(os_gamma, os_beta);
    attn_sim_kernel<<<dim3(GG/64, GG/64, NGRP), 256>>>();
    linkv_hmma_kernel<<<dim3(HHID/64, BB), 256, SMEM_LK>>>();
    fused_hmma_kernel<<<dim3(HHID/128, MROWS/128), 256, SMEM_MM>>>();

    // out = gated @ W_out + b_out + x  [8192, 1024]
    mm_bf16_kernel<2048,false,true,false><<<dim3(DD/128, MROWS/128), 256, SMEM_MM>>>(
        gated_bf, woT, b_out, x, out, nullptr, DD);
}

// round 9
// speedup vs baseline: 6.0427x; 1.0540x over previous
#include <cuda_runtime.h>
#include <cuda_bf16.h>
#include <math.h>
#include <cstdint>

// Problem constants
#define BB   4
#define SEQ  2048
#define DD   1024
#define GG   256
#define QKD  128
#define HHID 2048
#define MROWS (BB*SEQ)        // 8192
#define NGRP  (MROWS/GG)      // 32
#define TWOH  (2*HHID)        // 4096

// -------- device scratch (no cudaMalloc allowed) --------
__device__ __nv_bfloat16 g_normed_bf[(size_t)MROWS*DD];    // 16 MB
__device__ __nv_bfloat16 g_h_bf[(size_t)MROWS*TWOH];       // 64 MB (v | gate)
__device__ float g_qk[(size_t)MROWS*QKD];                  // 4 MB
__device__ __nv_bfloat16 g_quadq_bf[(size_t)MROWS*QKD];    // 2 MB
__device__ __nv_bfloat16 g_quadk_bf[(size_t)MROWS*QKD];    // 2 MB
__device__ __nv_bfloat16 g_linq_bf[(size_t)MROWS*QKD];     // 2 MB
__device__ __nv_bfloat16 g_linkT_bf[(size_t)BB*QKD*SEQ];   // 2 MB  lin_k^T [b][d][n]
__device__ __nv_bfloat16 g_attn_bf[(size_t)NGRP*GG*GG];    // 4 MB
__device__ __nv_bfloat16 g_linkv_bf[(size_t)BB*QKD*HHID];  // 2 MB
__device__ __nv_bfloat16 g_gated_bf[(size_t)MROWS*HHID];   // 32 MB
__device__ __nv_bfloat16 g_whT[(size_t)TWOH*DD];           // 8 MB
__device__ __nv_bfloat16 g_wqkT[(size_t)QKD*DD];           // 0.25 MB
__device__ __nv_bfloat16 g_woT[(size_t)DD*HHID];           // 4 MB
__device__ float g_sin[SEQ*64];
__device__ float g_cos[SEQ*64];

// =================== PTX helpers (arch-portable: sm_80+ subset) ===================
__device__ __forceinline__ uint32_t smem_u32(const void* p) {
    uint32_t a;
    asm("{ .reg .u64 t; cvta.to.shared.u64 t, %1; cvt.u32.u64 %0, t; }" : "=r"(a) : "l"(p));
    return a;
}
#define SW128(o) ((o) ^ (((o) >> 3) & 0x70))   // 128B rows
#define SWZ256(o) ((o) ^ (((o) >> 4) & 0x70))  // 256B rows

__device__ __forceinline__ void cpa16(uint32_t dst, const void* src) {
    asm volatile("cp.async.cg.shared.global [%0], [%1], 16;" :: "r"(dst), "l"(src));
}
#define CP_COMMIT() asm volatile("cp.async.commit_group;" ::: "memory")
#define CP_WAIT(n)  asm volatile("cp.async.wait_group %0;" :: "n"(n) : "memory")

__device__ __forceinline__ void ldsm_x4(uint32_t* r, uint32_t addr) {
    asm volatile("ldmatrix.sync.aligned.m8n8.x4.shared.b16 {%0,%1,%2,%3}, [%4];"
                 : "=r"(r[0]), "=r"(r[1]), "=r"(r[2]), "=r"(r[3]) : "r"(addr));
}
__device__ __forceinline__ void ldsm_x2(uint32_t* r, uint32_t addr) {
    asm volatile("ldmatrix.sync.aligned.m8n8.x2.shared.b16 {%0,%1}, [%2];"
                 : "=r"(r[0]), "=r"(r[1]) : "r"(addr));
}
__device__ __forceinline__ void ldsm_x4t(uint32_t* r, uint32_t addr) {
    asm volatile("ldmatrix.sync.aligned.m8n8.x4.trans.shared.b16 {%0,%1,%2,%3}, [%4];"
                 : "=r"(r[0]), "=r"(r[1]), "=r"(r[2]), "=r"(r[3]) : "r"(addr));
}
__device__ __forceinline__ void mma_16816(float* c, const uint32_t* a, const uint32_t* b) {
    asm volatile(
        "mma.sync.aligned.m16n8k16.row.col.f32.bf16.bf16.f32 "
        "{%0,%1,%2,%3}, {%4,%5,%6,%7}, {%8,%9}, {%0,%1,%2,%3};"
        : "+f"(c[0]), "+f"(c[1]), "+f"(c[2]), "+f"(c[3])
        : "r"(a[0]), "r"(a[1]), "r"(a[2]), "r"(a[3]), "r"(b[0]), "r"(b[1]));
}
__device__ __forceinline__ void st_bf2(__nv_bfloat16* p, float a, float b) {
    *(__nv_bfloat162*)p = __floats2bfloat162_rn(a, b);
}

// ====== bf16 tensor-core GEMM: C[M,N] = A[M,K] @ Bt[N,K]^T  (128x128 CTA tile) ======
template<int K_TOT, bool SILU_, bool RESID_, bool OUTBF_>
__global__ void __launch_bounds__(256)
mm_bf16_kernel(const __nv_bfloat16* __restrict__ A,
               const __nv_bfloat16* __restrict__ Bt,
               const float* __restrict__ bias,
               const float* __restrict__ resid,
               float* __restrict__ Cf, __nv_bfloat16* __restrict__ Cb, int ldC)
{
    constexpr int STAGES   = K_TOT / 64;
    constexpr int TILE_B   = 128 * 128;     // 16 KB
    extern __shared__ char smem[];
    const uint32_t aB = smem_u32(smem);
    const uint32_t bB = aB + 2 * TILE_B;

    const int tid = threadIdx.x, wid = tid >> 5, lane = tid & 31;
    const int m0 = blockIdx.y * 128, n0 = blockIdx.x * 128;
    const int wm = (wid >> 2) * 64;
    const int wn = (wid & 3) * 32;

    auto loadA = [&](int s, int buf) {
        uint32_t base = aB + buf * TILE_B;
        const __nv_bfloat16* src = A + (size_t)m0 * K_TOT + s * 64;
#pragma unroll
        for (int i = 0; i < 4; i++) {
            int c = tid + i * 256;
            int row = c >> 3, col = c & 7;
            cpa16(base + SW128(row * 128 + col * 16), src + (size_t)row * K_TOT + col * 8);
        }
    };
    auto loadB = [&](int s, int buf) {
        uint32_t base = bB + buf * TILE_B;
        const __nv_bfloat16* src = Bt + (size_t)n0 * K_TOT + s * 64;
#pragma unroll
        for (int i = 0; i < 4; i++) {
            int c = tid + i * 256;
            int row = c >> 3, col = c & 7;
            cpa16(base + SW128(row * 128 + col * 16), src + (size_t)row * K_TOT + col * 8);
        }
    };

    float acc[4][4][4] = {};
    const int a_row = wm + (lane & 15);
    const int a_kof = (lane >> 4) * 8;
    const int b_row = wn + (lane & 7);
    const int b_kof = ((lane >> 3) & 1) * 8;

    loadA(0, 0); loadB(0, 0); CP_COMMIT();

    for (int s = 0; s < STAGES; s++) {
        if (s + 1 < STAGES) {
            loadA(s + 1, (s + 1) & 1); loadB(s + 1, (s + 1) & 1);
            CP_COMMIT(); CP_WAIT(1);
        } else CP_WAIT(0);
        __syncthreads();
        const uint32_t abase = aB + (s & 1) * TILE_B;
        const uint32_t bbase = bB + (s & 1) * TILE_B;
#pragma unroll
        for (int ks = 0; ks < 4; ks++) {
            uint32_t af[4][4];
#pragma unroll
            for (int mi = 0; mi < 4; mi++)
                ldsm_x4(af[mi], abase + SW128((a_row + mi * 16) * 128 + (ks * 16 + a_kof) * 2));
            uint32_t bf[4][2];
#pragma unroll
            for (int ni = 0; ni < 4; ni++)
                ldsm_x2(bf[ni], bbase + SW128((b_row + ni * 8) * 128 + (ks * 16 + b_kof) * 2));
#pragma unroll
            for (int mi = 0; mi < 4; mi++)
#pragma unroll
                for (int ni = 0; ni < 4; ni++)
                    mma_16816(acc[mi][ni], af[mi], bf[ni]);
        }
        __syncthreads();
    }

    const int er = m0 + wm + (lane >> 2);
    const int ec = n0 + wn + (lane & 3) * 2;
#pragma unroll
    for (int mi = 0; mi < 4; mi++)
#pragma unroll
        for (int ni = 0; ni < 4; ni++) {
            int col = ec + ni * 8;
#pragma unroll
            for (int half = 0; half < 2; half++) {
                int row = er + mi * 16 + half * 8;
                float v0 = acc[mi][ni][half * 2 + 0] + bias[col + 0];
                float v1 = acc[mi][ni][half * 2 + 1] + bias[col + 1];
                if (SILU_) { v0 = v0 / (1.0f + expf(-v0)); v1 = v1 / (1.0f + expf(-v1)); }
                if (RESID_) {
                    v0 += resid[(size_t)row * ldC + col + 0];
                    v1 += resid[(size_t)row * ldC + col + 1];
                }
                if (OUTBF_) st_bf2(Cb + (size_t)row * ldC + col, v0, v1);
                else { float2 o; o.x = v0; o.y = v1; *(float2*)(Cf + (size_t)row * ldC + col) = o; }
            }
        }
}

// ====== attn HMMA: attn = relu(quad_q @ quad_k^T / g)^2 -> bf16  (128x128 tile) ======
__global__ void __launch_bounds__(256)
attn_hmma_kernel()
{
    constexpr int TILE_B = 128 * 128;   // 16 KB (128 rows x 64 K-cols bf16)
    extern __shared__ char smem[];
    const uint32_t aB = smem_u32(smem);
    const uint32_t bB = aB + 2 * TILE_B;

    const int tid = threadIdx.x, wid = tid >> 5, lane = tid & 31;
    const int gid = blockIdx.z;
    const int i0 = blockIdx.y * 128, j0 = blockIdx.x * 128;
    const int wm = (wid >> 2) * 64;
    const int wn = (wid & 3) * 32;

    const __nv_bfloat16* Aq = g_quadq_bf + ((size_t)gid * GG + i0) * QKD;
    const __nv_bfloat16* Bk = g_quadk_bf + ((size_t)gid * GG + j0) * QKD;

    auto loadT = [&](const __nv_bfloat16* src, uint32_t base, int s) {
        const __nv_bfloat16* p = src + s * 64;
#pragma unroll
        for (int i = 0; i < 4; i++) {
            int c = tid + i * 256;
            int row = c >> 3, col = c & 7;
            cpa16(base + SW128(row * 128 + col * 16), p + (size_t)row * QKD + col * 8);
        }
    };

    float acc[4][4][4] = {};
    const int a_row = wm + (lane & 15);
    const int a_kof = (lane >> 4) * 8;
    const int b_row = wn + (lane & 7);
    const int b_kof = ((lane >> 3) & 1) * 8;

    loadT(Aq, aB, 0); loadT(Bk, bB, 0); CP_COMMIT();
    for (int s = 0; s < 2; s++) {
        if (s + 1 < 2) {
            loadT(Aq, aB + TILE_B, 1); loadT(Bk, bB + TILE_B, 1);
            CP_COMMIT(); CP_WAIT(1);
        } else CP_WAIT(0);
        __syncthreads();
        const uint32_t abase = aB + s * TILE_B;
        const uint32_t bbase = bB + s * TILE_B;
#pragma unroll
        for (int ks = 0; ks < 4; ks++) {
            uint32_t af[4][4];
#pragma unroll
            for (int mi = 0; mi < 4; mi++)
                ldsm_x4(af[mi], abase + SW128((a_row + mi * 16) * 128 + (ks * 16 + a_kof) * 2));
            uint32_t bf[4][2];
#pragma unroll
            for (int ni = 0; ni < 4; ni++)
                ldsm_x2(bf[ni], bbase + SW128((b_row + ni * 8) * 128 + (ks * 16 + b_kof) * 2));
#pragma unroll
            for (int mi = 0; mi < 4; mi++)
#pragma unroll
                for (int ni = 0; ni < 4; ni++)
                    mma_16816(acc[mi][ni], af[mi], bf[ni]);
        }
        __syncthreads();
    }

    __nv_bfloat16* Cp = g_attn_bf + (size_t)gid * GG * GG;
    const int er = i0 + wm + (lane >> 2);
    const int ec = j0 + wn + (lane & 3) * 2;
#pragma unroll
    for (int mi = 0; mi < 4; mi++)
#pragma unroll
        for (int ni = 0; ni < 4; ni++) {
            int col = ec + ni * 8;
#pragma unroll
            for (int half = 0; half < 2; half++) {
                int row = er + mi * 16 + half * 8;
                float s0 = fmaxf(acc[mi][ni][half * 2 + 0] * (1.0f / GG), 0.0f);
                float s1 = fmaxf(acc[mi][ni][half * 2 + 1] * (1.0f / GG), 0.0f);
                st_bf2(Cp + (size_t)row * GG + col, s0 * s0, s1 * s1);
            }
        }
}

// ====== linkv HMMA: linkv[b,d,e] = sum_n lin_kT[b,d,n] * v[b,n,e] / SEQ ======
__global__ void __launch_bounds__(256)
linkv_hmma_kernel()
{
    constexpr int A_B = 128 * 128;
    constexpr int B_B = 64 * 128;
    extern __shared__ char smem[];
    const uint32_t aB = smem_u32(smem);
    const uint32_t bB = aB + 2 * A_B;

    const int tid = threadIdx.x, wid = tid >> 5, lane = tid & 31;
    const int b  = blockIdx.y;
    const int e0 = blockIdx.x * 64;
    const int wm = (wid & 3) * 32;
    const int wn = (wid >> 2) * 32;

    auto loadA = [&](int s, int buf) {
        uint32_t base = aB + buf * A_B;
        const __nv_bfloat16* src = g_linkT_bf + (size_t)b * QKD * SEQ + s * 64;
#pragma unroll
        for (int i = 0; i < 4; i++) {
            int c = tid + i * 256;
            int row = c >> 3, col = c & 7;
            cpa16(base + SW128(row * 128 + col * 16), src + (size_t)row * SEQ + col * 8);
        }
    };
    auto loadB = [&](int s, int buf) {
        uint32_t base = bB + buf * B_B;
        const __nv_bfloat16* src = g_h_bf + ((size_t)(b * SEQ + s * 64)) * TWOH + e0;
#pragma unroll
        for (int i = 0; i < 2; i++) {
            int c = tid + i * 256;
            int row = c >> 3, col = c & 7;
            cpa16(base + SW128(row * 128 + col * 16), src + (size_t)row * TWOH + col * 8);
        }
    };

    float acc[2][4][4] = {};
    const int a_row = wm + (lane & 15);
    const int a_kof = (lane >> 4) * 8;
    const int bt_k  = lane & 15;
    const int bt_n  = ((lane >> 4) & 1) * 8;

    loadA(0, 0); loadB(0, 0); CP_COMMIT();
    for (int s = 0; s < SEQ / 64; s++) {
        if (s + 1 < SEQ / 64) {
            loadA(s + 1, (s + 1) & 1); loadB(s + 1, (s + 1) & 1);
            CP_COMMIT(); CP_WAIT(1);
        } else CP_WAIT(0);
        __syncthreads();
        const uint32_t abase = aB + (s & 1) * A_B;
        const uint32_t bbase = bB + (s & 1) * B_B;
#pragma unroll
        for (int ks = 0; ks < 4; ks++) {
            uint32_t af[2][4];
#pragma unroll
            for (int mi = 0; mi < 2; mi++)
                ldsm_x4(af[mi], abase + SW128((a_row + mi * 16) * 128 + (ks * 16 + a_kof) * 2));
            uint32_t bt[2][4];
#pragma unroll
            for (int g = 0; g < 2; g++)
                ldsm_x4t(bt[g], bbase + SW128((ks * 16 + bt_k) * 128 + (wn + g * 16 + bt_n) * 2));
#pragma unroll
            for (int mi = 0; mi < 2; mi++)
#pragma unroll
                for (int g = 0; g < 2; g++) {
                    mma_16816(acc[mi][g * 2 + 0], af[mi], &bt[g][0]);
                    mma_16816(acc[mi][g * 2 + 1], af[mi], &bt[g][2]);
                }
        }
        __syncthreads();
    }

    __nv_bfloat16* Cp = g_linkv_bf + (size_t)b * QKD * HHID;
    const int er = wm + (lane >> 2);
    const int ec = e0 + wn + (lane & 3) * 2;
#pragma unroll
    for (int mi = 0; mi < 2; mi++)
#pragma unroll
        for (int ni = 0; ni < 4; ni++) {
            int col = ec + ni * 8;
#pragma unroll
            for (int half = 0; half < 2; half++) {
                int row = er + mi * 16 + half * 8;
                st_bf2(Cp + (size_t)row * HHID + col,
                       acc[mi][ni][half * 2 + 0] * (1.0f / SEQ),
                       acc[mi][ni][half * 2 + 1] * (1.0f / SEQ));
            }
        }
}

// ====== fused HMMA: gated = gate * (attn@v + lin_q@lin_kv)  (128p x 128e tile) ======
__global__ void __launch_bounds__(256)
fused_hmma_kernel()
{
    constexpr int TILE_B = 128 * 128;
    extern __shared__ char smem[];
    const uint32_t aB = smem_u32(smem);
    const uint32_t bB = aB + 2 * TILE_B;

    const int tid = threadIdx.x, wid = tid >> 5, lane = tid & 31;
    const int p0 = blockIdx.y * 128, e0 = blockIdx.x * 128;
    const int gid = p0 >> 8, b = p0 >> 11, i0 = p0 & 255;
    const int wm = (wid >> 2) * 64;
    const int wn = (wid & 3) * 32;

    auto loadStage = [&](int s, int buf) {
        uint32_t abase = aB + buf * TILE_B;
        uint32_t bbase = bB + buf * TILE_B;
        if (s < 4) {
            const __nv_bfloat16* asrc = g_attn_bf + (size_t)gid * GG * GG + (size_t)i0 * GG + s * 64;
#pragma unroll
            for (int i = 0; i < 4; i++) {
                int c = tid + i * 256;
                int row = c >> 3, col = c & 7;
                cpa16(abase + SW128(row * 128 + col * 16), asrc + (size_t)row * GG + col * 8);
            }
            const __nv_bfloat16* bsrc = g_h_bf + ((size_t)(gid * GG + s * 64)) * TWOH + e0;
#pragma unroll
            for (int i = 0; i < 4; i++) {
                int c = tid + i * 256;
                int row = c >> 4, col = c & 15;
                cpa16(bbase + SWZ256(row * 256 + col * 16), bsrc + (size_t)row * TWOH + col * 8);
            }
        } else {
            int s2 = s - 4;
            const __nv_bfloat16* asrc = g_linq_bf + (size_t)p0 * QKD + s2 * 64;
#pragma unroll
            for (int i = 0; i < 4; i++) {
                int c = tid + i * 256;
                int row = c >> 3, col = c & 7;
                cpa16(abase + SW128(row * 128 + col * 16), asrc + (size_t)row * QKD + col * 8);
            }
            const __nv_bfloat16* bsrc = g_linkv_bf + (size_t)b * QKD * HHID + (size_t)(s2 * 64) * HHID + e0;
#pragma unroll
            for (int i = 0; i < 4; i++) {
                int c = tid + i * 256;
                int row = c >> 4, col = c & 15;
                cpa16(bbase + SWZ256(row * 256 + col * 16), bsrc + (size_t)row * TWOH / 2 + col * 8);
            }
        }
    };

    float acc[4][4][4] = {};
    const int a_row = wm + (lane & 15);
    const int a_kof = (lane >> 4) * 8;
    const int bt_k  = lane & 15;
    const int bt_n  = ((lane >> 4) & 1) * 8;

    loadStage(0, 0); CP_COMMIT();
    for (int s = 0; s < 6; s++) {
        if (s + 1 < 6) { loadStage(s + 1, (s + 1) & 1); CP_COMMIT(); CP_WAIT(1); }
        else CP_WAIT(0);
        __syncthreads();
        const uint32_t abase = aB + (s & 1) * TILE_B;
        const uint32_t bbase = bB + (s & 1) * TILE_B;
#pragma unroll
        for (int ks = 0; ks < 4; ks++) {
            uint32_t af[4][4];
#pragma unroll
            for (int mi = 0; mi < 4; mi++)
                ldsm_x4(af[mi], abase + SW128((a_row + mi * 16) * 128 + (ks * 16 + a_kof) * 2));
            uint32_t bt[2][4];
#pragma unroll
            for (int g = 0; g < 2; g++)
                ldsm_x4t(bt[g], bbase + SWZ256((ks * 16 + bt_k) * 256 + (wn + g * 16 + bt_n) * 2));
#pragma unroll
            for (int mi = 0; mi < 4; mi++)
#pragma unroll
                for (int g = 0; g < 2; g++) {
                    mma_16816(acc[mi][g * 2 + 0], af[mi], &bt[g][0]);
                    mma_16816(acc[mi][g * 2 + 1], af[mi], &bt[g][2]);
                }
        }
        __syncthreads();
    }

    const int er = p0 + wm + (lane >> 2);
    const int ec = e0 + wn + (lane & 3) * 2;
#pragma unroll
    for (int mi = 0; mi < 4; mi++)
#pragma unroll
        for (int ni = 0; ni < 4; ni++) {
            int col = ec + ni * 8;
#pragma unroll
            for (int half = 0; half < 2; half++) {
                int row = er + mi * 16 + half * 8;
                float g0 = __bfloat162float(g_h_bf[(size_t)row * TWOH + HHID + col + 0]);
                float g1 = __bfloat162float(g_h_bf[(size_t)row * TWOH + HHID + col + 1]);
                st_bf2(g_gated_bf + (size_t)row * HHID + col,
                       g0 * acc[mi][ni][half * 2 + 0], g1 * acc[mi][ni][half * 2 + 1]);
            }
        }
}

// =================== transpose + fp32->bf16 convert ==========
__global__ void transpose_bf_kernel(const float* __restrict__ in,
                                    __nv_bfloat16* __restrict__ out, int R, int Cc) {
    __shared__ float t[32][33];
    int c0 = blockIdx.x * 32, r0 = blockIdx.y * 32;
    int x = threadIdx.x, y = threadIdx.y;
#pragma unroll
    for (int i = 0; i < 32; i += 8)
        t[y + i][x] = in[(size_t)(r0 + y + i) * Cc + c0 + x];
    __syncthreads();
#pragma unroll
    for (int i = 0; i < 32; i += 8)
        out[(size_t)(c0 + y + i) * R + r0 + x] = __float2bfloat16(t[x][y + i]);
}

// ------- RoPE tables: one block per frequency j; fp64 pow runs 64x total -------
__global__ void rope_table_kernel() {
    int j = blockIdx.x;
    float invf = (float)pow(10000.0, (double)j / 64.0);
    for (int n = threadIdx.x; n < SEQ; n += blockDim.x) {
        float ang = (float)n * invf;
        g_sin[n*64 + j] = sinf(ang);
        g_cos[n*64 + j] = cosf(ang);
    }
}

// ---------------- LayerNorm (emits bf16 A operand) ----------------
__global__ void ln_kernel(const float* __restrict__ x,
                          const float* __restrict__ gam,
                          const float* __restrict__ bet) {
    int row = blockIdx.x, t = threadIdx.x;
    const float* xr = x + (size_t)row * DD;
    float v[4]; float s = 0.f;
#pragma unroll
    for (int c = 0; c < 4; c++) { v[c] = xr[t + 256*c]; s += v[c]; }
    __shared__ float red[8];
    __shared__ float bcast;
    int lane = t & 31, w = t >> 5;
#pragma unroll
    for (int o = 16; o; o >>= 1) s += __shfl_xor_sync(~0u, s, o);
    if (lane == 0) red[w] = s;
    __syncthreads();
    if (t == 0) { float tot = 0; for (int i = 0; i < 8; i++) tot += red[i]; bcast = tot / DD; }
    __syncthreads();
    float mu = bcast;
    float s2 = 0.f;
#pragma unroll
    for (int c = 0; c < 4; c++) { float d = v[c] - mu; s2 += d * d; }
#pragma unroll
    for (int o = 16; o; o >>= 1) s2 += __shfl_xor_sync(~0u, s2, o);
    __syncthreads();
    if (lane == 0) red[w] = s2;
    __syncthreads();
    if (t == 0) { float tot = 0; for (int i = 0; i < 8; i++) tot += red[i];
                  bcast = 1.0f / sqrtf(tot / DD + 1e-5f); }
    __syncthreads();
    float rstd = bcast;
    __nv_bfloat16* out = g_normed_bf + (size_t)row * DD;
#pragma unroll
    for (int c = 0; c < 4; c++) {
        int d = t + 256*c;
        out[d] = __float2bfloat16((v[c] - mu) * rstd * gam[d] + bet[d]);
    }
}

// -------- OffsetScale + RoPE: all four heads -> bf16 --------
__global__ void rope_apply_kernel(const float* __restrict__ gamma,
                                  const float* __restrict__ beta) {
    int tid = threadIdx.x;
    int tok = blockIdx.x * 4 + (tid >> 6);
    int j   = tid & 63;
    int n   = tok & (SEQ - 1);
    int b   = tok >> 11;
    float v1 = g_qk[(size_t)tok * QKD + j];
    float v2 = g_qk[(size_t)tok * QKD + j + 64];
    float sn = g_sin[n*64 + j], cs = g_cos[n*64 + j];
    // h=0: quad_q
    {
        float a1 = v1 * gamma[0*QKD + j]      + beta[0*QKD + j];
        float a2 = v2 * gamma[0*QKD + j + 64] + beta[0*QKD + j + 64];
        g_quadq_bf[(size_t)tok * QKD + j]      = __float2bfloat16(a1 * cs - a2 * sn);
        g_quadq_bf[(size_t)tok * QKD + j + 64] = __float2bfloat16(a2 * cs + a1 * sn);
    }
    // h=2: quad_k
    {
        float a1 = v1 * gamma[2*QKD + j]      + beta[2*QKD + j];
        float a2 = v2 * gamma[2*QKD + j + 64] + beta[2*QKD + j + 64];
        g_quadk_bf[(size_t)tok * QKD + j]      = __float2bfloat16(a1 * cs - a2 * sn);
        g_quadk_bf[(size_t)tok * QKD + j + 64] = __float2bfloat16(a2 * cs + a1 * sn);
    }
    // h=1: lin_q
    {
        float a1 = v1 * gamma[1*QKD + j]      + beta[1*QKD + j];
        float a2 = v2 * gamma[1*QKD + j + 64] + beta[1*QKD + j + 64];
        g_linq_bf[(size_t)tok * QKD + j]      = __float2bfloat16(a1 * cs - a2 * sn);
        g_linq_bf[(size_t)tok * QKD + j + 64] = __float2bfloat16(a2 * cs + a1 * sn);
    }
    // h=3: lin_k transposed [b][d][n]
    {
        float a1 = v1 * gamma[3*QKD + j]      + beta[3*QKD + j];
        float a2 = v2 * gamma[3*QKD + j + 64] + beta[3*QKD + j + 64];
        __nv_bfloat16* base = g_linkT_bf + (size_t)b * QKD * SEQ;
        base[(size_t)j * SEQ + n]        = __float2bfloat16(a1 * cs - a2 * sn);
        base[(size_t)(j + 64) * SEQ + n] = __float2bfloat16(a2 * cs + a1 * sn);
    }
}

// ---------------------------------------------------------------------------
extern "C" void kernel_launch(void* const* d_in, const int* in_sizes, int n_in,
                              void* d_out, int out_size) {
    const float* x        = (const float*)d_in[0];
    const float* ln_g     = (const float*)d_in[1];
    const float* ln_b     = (const float*)d_in[2];
    const float* W_hidden = (const float*)d_in[3];
    const float* b_hidden = (const float*)d_in[4];
    const float* W_qk     = (const float*)d_in[5];
    const float* b_qk     = (const float*)d_in[6];
    const float* os_gamma = (const float*)d_in[7];
    const float* os_beta  = (const float*)d_in[8];
    const float* W_out    = (const float*)d_in[9];
    const float* b_out    = (const float*)d_in[10];
    float* out = (float*)d_out;

    __nv_bfloat16 *normed_bf, *whT, *wqkT, *woT, *gated_bf, *h_bf;
    float *qk;
    cudaGetSymbolAddress((void**)&normed_bf, g_normed_bf);
    cudaGetSymbolAddress((void**)&whT,  g_whT);
    cudaGetSymbolAddress((void**)&wqkT, g_wqkT);
    cudaGetSymbolAddress((void**)&woT,  g_woT);
    cudaGetSymbolAddress((void**)&gated_bf, g_gated_bf);
    cudaGetSymbolAddress((void**)&h_bf, g_h_bf);
    cudaGetSymbolAddress((void**)&qk, g_qk);

    const int SMEM_MM = 4 * 128 * 128;          // 64 KB
    const int SMEM_LK = 2 * 16384 + 2 * 8192;   // 48 KB
    cudaFuncSetAttribute(mm_bf16_kernel<1024,true,false,true>,
                         cudaFuncAttributeMaxDynamicSharedMemorySize, SMEM_MM);
    cudaFuncSetAttribute(mm_bf16_kernel<1024,true,false,false>,
                         cudaFuncAttributeMaxDynamicSharedMemorySize, SMEM_MM);
    cudaFuncSetAttribute(mm_bf16_kernel<2048,false,true,false>,
                         cudaFuncAttributeMaxDynamicSharedMemorySize, SMEM_MM);
    cudaFuncSetAttribute(attn_hmma_kernel,
                         cudaFuncAttributeMaxDynamicSharedMemorySize, SMEM_MM);
    cudaFuncSetAttribute(linkv_hmma_kernel,
                         cudaFuncAttributeMaxDynamicSharedMemorySize, SMEM_LK);
    cudaFuncSetAttribute(fused_hmma_kernel,
                         cudaFuncAttributeMaxDynamicSharedMemorySize, SMEM_MM);

    transpose_bf_kernel<<<dim3(TWOH/32, DD/32), dim3(32,8)>>>(W_hidden, whT, DD, TWOH);
    transpose_bf_kernel<<<dim3(QKD/32,  DD/32), dim3(32,8)>>>(W_qk,  wqkT, DD, QKD);
    transpose_bf_kernel<<<dim3(DD/32, HHID/32), dim3(32,8)>>>(W_out, woT,  HHID, DD);

    rope_table_kernel<<<64, 256>>>();
    ln_kernel<<<MROWS, 256>>>(x, ln_g, ln_b);

    // h = silu(normed @ W_hidden + b) -> bf16 [8192, 4096]
    mm_bf16_kernel<1024,true,false,true><<<dim3(TWOH/128, MROWS/128), 256, SMEM_MM>>>(
        normed_bf, whT, b_hidden, nullptr, nullptr, h_bf, TWOH);
    // qk = silu(normed @ W_qk + b) -> fp32 [8192, 128]
    mm_bf16_kernel<1024,true,false,false><<<dim3(QKD/128, MROWS/128), 256, SMEM_MM>>>(
        normed_bf, wqkT, b_qk, nullptr, qk, nullptr, QKD);

    rope_apply_kernel<<<MROWS/4, 256>>>(os_gamma, os_beta);
    attn_hmma_kernel<<<dim3(GG/128, GG/128, NGRP), 256, SMEM_MM>>>();
    linkv_hmma_kernel<<<dim3(HHID/64, BB), 256, SMEM_LK>>>();
    fused_hmma_kernel<<<dim3(HHID/128, MROWS/128), 256, SMEM_MM>>>();

    // out = gated @ W_out + b_out + x  [8192, 1024]
    mm_bf16_kernel<2048,false,true,false><<<dim3(DD/128, MROWS/128), 256, SMEM_MM>>>(
        gated_bf, woT, b_out, x, out, nullptr, DD);
}

// round 10
// speedup vs baseline: 6.3243x; 1.0466x over previous
#include <cuda_runtime.h>
#include <cuda_bf16.h>
#include <math.h>
#include <cstdint>

// Problem constants
#define BB   4
#define SEQ  2048
#define DD   1024
#define GG   256
#define QKD  128
#define HHID 2048
#define MROWS (BB*SEQ)        // 8192
#define NGRP  (MROWS/GG)      // 32
#define TWOH  (2*HHID)        // 4096

// -------- device scratch (no cudaMalloc allowed) --------
__device__ __nv_bfloat16 g_normed_bf[(size_t)MROWS*DD];    // 16 MB
__device__ __nv_bfloat16 g_h_bf[(size_t)MROWS*TWOH];       // 64 MB (v | gate)
__device__ float g_qk[(size_t)MROWS*QKD];                  // 4 MB
__device__ __nv_bfloat16 g_quadq_bf[(size_t)MROWS*QKD];    // 2 MB
__device__ __nv_bfloat16 g_quadk_bf[(size_t)MROWS*QKD];    // 2 MB
__device__ __nv_bfloat16 g_linq_bf[(size_t)MROWS*QKD];     // 2 MB
__device__ __nv_bfloat16 g_linkT_bf[(size_t)BB*QKD*SEQ];   // 2 MB  lin_k^T [b][d][n]
__device__ __nv_bfloat16 g_attn_bf[(size_t)NGRP*GG*GG];    // 4 MB
__device__ __nv_bfloat16 g_linkv_bf[(size_t)BB*QKD*HHID];  // 2 MB
__device__ __nv_bfloat16 g_gated_bf[(size_t)MROWS*HHID];   // 32 MB
__device__ __nv_bfloat16 g_whT[(size_t)TWOH*DD];           // 8 MB
__device__ __nv_bfloat16 g_wqkT[(size_t)QKD*DD];           // 0.25 MB
__device__ __nv_bfloat16 g_woT[(size_t)DD*HHID];           // 4 MB
__device__ float g_sin[SEQ*64];
__device__ float g_cos[SEQ*64];

// =================== PTX helpers (arch-portable: sm_80+ subset) ===================
__device__ __forceinline__ uint32_t smem_u32(const void* p) {
    uint32_t a;
    asm("{ .reg .u64 t; cvta.to.shared.u64 t, %1; cvt.u32.u64 %0, t; }" : "=r"(a) : "l"(p));
    return a;
}
#define SW128(o) ((o) ^ (((o) >> 3) & 0x70))   // 128B rows
#define SWZ256(o) ((o) ^ (((o) >> 4) & 0x70))  // 256B rows

__device__ __forceinline__ void cpa16(uint32_t dst, const void* src) {
    asm volatile("cp.async.cg.shared.global [%0], [%1], 16;" :: "r"(dst), "l"(src));
}
#define CP_COMMIT() asm volatile("cp.async.commit_group;" ::: "memory")
#define CP_WAIT(n)  asm volatile("cp.async.wait_group %0;" :: "n"(n) : "memory")

__device__ __forceinline__ void ldsm_x4(uint32_t* r, uint32_t addr) {
    asm volatile("ldmatrix.sync.aligned.m8n8.x4.shared.b16 {%0,%1,%2,%3}, [%4];"
                 : "=r"(r[0]), "=r"(r[1]), "=r"(r[2]), "=r"(r[3]) : "r"(addr));
}
__device__ __forceinline__ void ldsm_x2(uint32_t* r, uint32_t addr) {
    asm volatile("ldmatrix.sync.aligned.m8n8.x2.shared.b16 {%0,%1}, [%2];"
                 : "=r"(r[0]), "=r"(r[1]) : "r"(addr));
}
__device__ __forceinline__ void ldsm_x4t(uint32_t* r, uint32_t addr) {
    asm volatile("ldmatrix.sync.aligned.m8n8.x4.trans.shared.b16 {%0,%1,%2,%3}, [%4];"
                 : "=r"(r[0]), "=r"(r[1]), "=r"(r[2]), "=r"(r[3]) : "r"(addr));
}
__device__ __forceinline__ void mma_16816(float* c, const uint32_t* a, const uint32_t* b) {
    asm volatile(
        "mma.sync.aligned.m16n8k16.row.col.f32.bf16.bf16.f32 "
        "{%0,%1,%2,%3}, {%4,%5,%6,%7}, {%8,%9}, {%0,%1,%2,%3};"
        : "+f"(c[0]), "+f"(c[1]), "+f"(c[2]), "+f"(c[3])
        : "r"(a[0]), "r"(a[1]), "r"(a[2]), "r"(a[3]), "r"(b[0]), "r"(b[1]));
}
__device__ __forceinline__ void st_bf2(__nv_bfloat16* p, float a, float b) {
    *(__nv_bfloat162*)p = __floats2bfloat162_rn(a, b);
}

// ====== bf16 tensor-core GEMM: C[M,N] = A[M,K] @ Bt[N,K]^T ======
// CTA tile 128 x N_CTA (128 or 256), 8 warps (2 x 4), warp tile 64 x (N_CTA/4).
// 3-stage cp.async ring.
template<int N_CTA, int K_TOT, bool SILU_, bool RESID_, bool OUTBF_>
__global__ void __launch_bounds__(256, 1)
mm_bf16_kernel(const __nv_bfloat16* __restrict__ A,
               const __nv_bfloat16* __restrict__ Bt,
               const float* __restrict__ bias,
               const float* __restrict__ resid,
               float* __restrict__ Cf, __nv_bfloat16* __restrict__ Cb, int ldC)
{
    constexpr int STAGES = K_TOT / 64;
    constexpr int A_B    = 128 * 128;       // 16 KB
    constexpr int B_B    = N_CTA * 128;     // 16/32 KB
    constexpr int NI     = N_CTA / 32;      // mma n-tiles per warp (4 or 8)
    constexpr int NBCH   = N_CTA / 32;      // loadB chunks per thread
    extern __shared__ char smem[];
    const uint32_t aB = smem_u32(smem);
    const uint32_t bB = aB + 3 * A_B;

    const int tid = threadIdx.x, wid = tid >> 5, lane = tid & 31;
    const int m0 = blockIdx.y * 128, n0 = blockIdx.x * N_CTA;
    const int wm = (wid >> 2) * 64;
    const int wn = (wid & 3) * (N_CTA / 4);

    auto loadA = [&](int s, int buf) {
        uint32_t base = aB + buf * A_B;
        const __nv_bfloat16* src = A + (size_t)m0 * K_TOT + s * 64;
#pragma unroll
        for (int i = 0; i < 4; i++) {
            int c = tid + i * 256;
            int row = c >> 3, col = c & 7;
            cpa16(base + SW128(row * 128 + col * 16), src + (size_t)row * K_TOT + col * 8);
        }
    };
    auto loadB = [&](int s, int buf) {
        uint32_t base = bB + buf * B_B;
        const __nv_bfloat16* src = Bt + (size_t)n0 * K_TOT + s * 64;
#pragma unroll
        for (int i = 0; i < NBCH; i++) {
            int c = tid + i * 256;
            int row = c >> 3, col = c & 7;
            cpa16(base + SW128(row * 128 + col * 16), src + (size_t)row * K_TOT + col * 8);
        }
    };

    float acc[4][NI][4] = {};
    const int a_row = wm + (lane & 15);
    const int a_kof = (lane >> 4) * 8;
    const int b_row = wn + (lane & 7);
    const int b_kof = ((lane >> 3) & 1) * 8;

    loadA(0, 0); loadB(0, 0); CP_COMMIT();
    if (STAGES > 1) { loadA(1, 1); loadB(1, 1); CP_COMMIT(); }

    for (int s = 0; s < STAGES; s++) {
        if (s + 2 < STAGES) {
            loadA(s + 2, (s + 2) % 3); loadB(s + 2, (s + 2) % 3);
            CP_COMMIT(); CP_WAIT(2);
        } else if (s + 1 < STAGES) CP_WAIT(1);
        else CP_WAIT(0);
        __syncthreads();
        const uint32_t abase = aB + (s % 3) * A_B;
        const uint32_t bbase = bB + (s % 3) * B_B;
#pragma unroll
        for (int ks = 0; ks < 4; ks++) {
            uint32_t af[4][4];
#pragma unroll
            for (int mi = 0; mi < 4; mi++)
                ldsm_x4(af[mi], abase + SW128((a_row + mi * 16) * 128 + (ks * 16 + a_kof) * 2));
            uint32_t bf[NI][2];
#pragma unroll
            for (int ni = 0; ni < NI; ni++)
                ldsm_x2(bf[ni], bbase + SW128((b_row + ni * 8) * 128 + (ks * 16 + b_kof) * 2));
#pragma unroll
            for (int mi = 0; mi < 4; mi++)
#pragma unroll
                for (int ni = 0; ni < NI; ni++)
                    mma_16816(acc[mi][ni], af[mi], bf[ni]);
        }
        __syncthreads();
    }

    const int er = m0 + wm + (lane >> 2);
    const int ec = n0 + wn + (lane & 3) * 2;
#pragma unroll
    for (int mi = 0; mi < 4; mi++)
#pragma unroll
        for (int ni = 0; ni < NI; ni++) {
            int col = ec + ni * 8;
#pragma unroll
            for (int half = 0; half < 2; half++) {
                int row = er + mi * 16 + half * 8;
                float v0 = acc[mi][ni][half * 2 + 0] + bias[col + 0];
                float v1 = acc[mi][ni][half * 2 + 1] + bias[col + 1];
                if (SILU_) { v0 = v0 / (1.0f + expf(-v0)); v1 = v1 / (1.0f + expf(-v1)); }
                if (RESID_) {
                    v0 += resid[(size_t)row * ldC + col + 0];
                    v1 += resid[(size_t)row * ldC + col + 1];
                }
                if (OUTBF_) st_bf2(Cb + (size_t)row * ldC + col, v0, v1);
                else { float2 o; o.x = v0; o.y = v1; *(float2*)(Cf + (size_t)row * ldC + col) = o; }
            }
        }
}

// ====== attn HMMA: attn = relu(quad_q @ quad_k^T / g)^2 -> bf16  (128x128 tile) ======
__global__ void __launch_bounds__(256)
attn_hmma_kernel()
{
    constexpr int TILE_B = 128 * 128;
    extern __shared__ char smem[];
    const uint32_t aB = smem_u32(smem);
    const uint32_t bB = aB + 2 * TILE_B;

    const int tid = threadIdx.x, wid = tid >> 5, lane = tid & 31;
    const int gid = blockIdx.z;
    const int i0 = blockIdx.y * 128, j0 = blockIdx.x * 128;
    const int wm = (wid >> 2) * 64;
    const int wn = (wid & 3) * 32;

    const __nv_bfloat16* Aq = g_quadq_bf + ((size_t)gid * GG + i0) * QKD;
    const __nv_bfloat16* Bk = g_quadk_bf + ((size_t)gid * GG + j0) * QKD;

    auto loadT = [&](const __nv_bfloat16* src, uint32_t base, int s) {
        const __nv_bfloat16* p = src + s * 64;
#pragma unroll
        for (int i = 0; i < 4; i++) {
            int c = tid + i * 256;
            int row = c >> 3, col = c & 7;
            cpa16(base + SW128(row * 128 + col * 16), p + (size_t)row * QKD + col * 8);
        }
    };

    float acc[4][4][4] = {};
    const int a_row = wm + (lane & 15);
    const int a_kof = (lane >> 4) * 8;
    const int b_row = wn + (lane & 7);
    const int b_kof = ((lane >> 3) & 1) * 8;

    loadT(Aq, aB, 0); loadT(Bk, bB, 0); CP_COMMIT();
    for (int s = 0; s < 2; s++) {
        if (s + 1 < 2) {
            loadT(Aq, aB + TILE_B, 1); loadT(Bk, bB + TILE_B, 1);
            CP_COMMIT(); CP_WAIT(1);
        } else CP_WAIT(0);
        __syncthreads();
        const uint32_t abase = aB + s * TILE_B;
        const uint32_t bbase = bB + s * TILE_B;
#pragma unroll
        for (int ks = 0; ks < 4; ks++) {
            uint32_t af[4][4];
#pragma unroll
            for (int mi = 0; mi < 4; mi++)
                ldsm_x4(af[mi], abase + SW128((a_row + mi * 16) * 128 + (ks * 16 + a_kof) * 2));
            uint32_t bf[4][2];
#pragma unroll
            for (int ni = 0; ni < 4; ni++)
                ldsm_x2(bf[ni], bbase + SW128((b_row + ni * 8) * 128 + (ks * 16 + b_kof) * 2));
#pragma unroll
            for (int mi = 0; mi < 4; mi++)
#pragma unroll
                for (int ni = 0; ni < 4; ni++)
                    mma_16816(acc[mi][ni], af[mi], bf[ni]);
        }
        __syncthreads();
    }

    __nv_bfloat16* Cp = g_attn_bf + (size_t)gid * GG * GG;
    const int er = i0 + wm + (lane >> 2);
    const int ec = j0 + wn + (lane & 3) * 2;
#pragma unroll
    for (int mi = 0; mi < 4; mi++)
#pragma unroll
        for (int ni = 0; ni < 4; ni++) {
            int col = ec + ni * 8;
#pragma unroll
            for (int half = 0; half < 2; half++) {
                int row = er + mi * 16 + half * 8;
                float s0 = fmaxf(acc[mi][ni][half * 2 + 0] * (1.0f / GG), 0.0f);
                float s1 = fmaxf(acc[mi][ni][half * 2 + 1] * (1.0f / GG), 0.0f);
                st_bf2(Cp + (size_t)row * GG + col, s0 * s0, s1 * s1);
            }
        }
}

// ====== linkv HMMA: linkv[b,d,e] = sum_n lin_kT[b,d,n] * v[b,n,e] / SEQ ======
__global__ void __launch_bounds__(256)
linkv_hmma_kernel()
{
    constexpr int A_B = 128 * 128;
    constexpr int B_B = 64 * 128;
    extern __shared__ char smem[];
    const uint32_t aB = smem_u32(smem);
    const uint32_t bB = aB + 2 * A_B;

    const int tid = threadIdx.x, wid = tid >> 5, lane = tid & 31;
    const int b  = blockIdx.y;
    const int e0 = blockIdx.x * 64;
    const int wm = (wid & 3) * 32;
    const int wn = (wid >> 2) * 32;

    auto loadA = [&](int s, int buf) {
        uint32_t base = aB + buf * A_B;
        const __nv_bfloat16* src = g_linkT_bf + (size_t)b * QKD * SEQ + s * 64;
#pragma unroll
        for (int i = 0; i < 4; i++) {
            int c = tid + i * 256;
            int row = c >> 3, col = c & 7;
            cpa16(base + SW128(row * 128 + col * 16), src + (size_t)row * SEQ + col * 8);
        }
    };
    auto loadB = [&](int s, int buf) {
        uint32_t base = bB + buf * B_B;
        const __nv_bfloat16* src = g_h_bf + ((size_t)(b * SEQ + s * 64)) * TWOH + e0;
#pragma unroll
        for (int i = 0; i < 2; i++) {
            int c = tid + i * 256;
            int row = c >> 3, col = c & 7;
            cpa16(base + SW128(row * 128 + col * 16), src + (size_t)row * TWOH + col * 8);
        }
    };

    float acc[2][4][4] = {};
    const int a_row = wm + (lane & 15);
    const int a_kof = (lane >> 4) * 8;
    const int bt_k  = lane & 15;
    const int bt_n  = ((lane >> 4) & 1) * 8;

    loadA(0, 0); loadB(0, 0); CP_COMMIT();
    for (int s = 0; s < SEQ / 64; s++) {
        if (s + 1 < SEQ / 64) {
            loadA(s + 1, (s + 1) & 1); loadB(s + 1, (s + 1) & 1);
            CP_COMMIT(); CP_WAIT(1);
        } else CP_WAIT(0);
        __syncthreads();
        const uint32_t abase = aB + (s & 1) * A_B;
        const uint32_t bbase = bB + (s & 1) * B_B;
#pragma unroll
        for (int ks = 0; ks < 4; ks++) {
            uint32_t af[2][4];
#pragma unroll
            for (int mi = 0; mi < 2; mi++)
                ldsm_x4(af[mi], abase + SW128((a_row + mi * 16) * 128 + (ks * 16 + a_kof) * 2));
            uint32_t bt[2][4];
#pragma unroll
            for (int g = 0; g < 2; g++)
                ldsm_x4t(bt[g], bbase + SW128((ks * 16 + bt_k) * 128 + (wn + g * 16 + bt_n) * 2));
#pragma unroll
            for (int mi = 0; mi < 2; mi++)
#pragma unroll
                for (int g = 0; g < 2; g++) {
                    mma_16816(acc[mi][g * 2 + 0], af[mi], &bt[g][0]);
                    mma_16816(acc[mi][g * 2 + 1], af[mi], &bt[g][2]);
                }
        }
        __syncthreads();
    }

    __nv_bfloat16* Cp = g_linkv_bf + (size_t)b * QKD * HHID;
    const int er = wm + (lane >> 2);
    const int ec = e0 + wn + (lane & 3) * 2;
#pragma unroll
    for (int mi = 0; mi < 2; mi++)
#pragma unroll
        for (int ni = 0; ni < 4; ni++) {
            int col = ec + ni * 8;
#pragma unroll
            for (int half = 0; half < 2; half++) {
                int row = er + mi * 16 + half * 8;
                st_bf2(Cp + (size_t)row * HHID + col,
                       acc[mi][ni][half * 2 + 0] * (1.0f / SEQ),
                       acc[mi][ni][half * 2 + 1] * (1.0f / SEQ));
            }
        }
}

// ====== fused HMMA: gated = gate * (attn@v + lin_q@lin_kv)  (128p x 128e tile) ======
__global__ void __launch_bounds__(256)
fused_hmma_kernel()
{
    constexpr int TILE_B = 128 * 128;
    extern __shared__ char smem[];
    const uint32_t aB = smem_u32(smem);
    const uint32_t bB = aB + 2 * TILE_B;

    const int tid = threadIdx.x, wid = tid >> 5, lane = tid & 31;
    const int p0 = blockIdx.y * 128, e0 = blockIdx.x * 128;
    const int gid = p0 >> 8, b = p0 >> 11, i0 = p0 & 255;
    const int wm = (wid >> 2) * 64;
    const int wn = (wid & 3) * 32;

    auto loadStage = [&](int s, int buf) {
        uint32_t abase = aB + buf * TILE_B;
        uint32_t bbase = bB + buf * TILE_B;
        if (s < 4) {
            const __nv_bfloat16* asrc = g_attn_bf + (size_t)gid * GG * GG + (size_t)i0 * GG + s * 64;
#pragma unroll
            for (int i = 0; i < 4; i++) {
                int c = tid + i * 256;
                int row = c >> 3, col = c & 7;
                cpa16(abase + SW128(row * 128 + col * 16), asrc + (size_t)row * GG + col * 8);
            }
            const __nv_bfloat16* bsrc = g_h_bf + ((size_t)(gid * GG + s * 64)) * TWOH + e0;
#pragma unroll
            for (int i = 0; i < 4; i++) {
                int c = tid + i * 256;
                int row = c >> 4, col = c & 15;
                cpa16(bbase + SWZ256(row * 256 + col * 16), bsrc + (size_t)row * TWOH + col * 8);
            }
        } else {
            int s2 = s - 4;
            const __nv_bfloat16* asrc = g_linq_bf + (size_t)p0 * QKD + s2 * 64;
#pragma unroll
            for (int i = 0; i < 4; i++) {
                int c = tid + i * 256;
                int row = c >> 3, col = c & 7;
                cpa16(abase + SW128(row * 128 + col * 16), asrc + (size_t)row * QKD + col * 8);
            }
            const __nv_bfloat16* bsrc = g_linkv_bf + (size_t)b * QKD * HHID + (size_t)(s2 * 64) * HHID + e0;
#pragma unroll
            for (int i = 0; i < 4; i++) {
                int c = tid + i * 256;
                int row = c >> 4, col = c & 15;
                cpa16(bbase + SWZ256(row * 256 + col * 16), bsrc + (size_t)row * TWOH / 2 + col * 8);
            }
        }
    };

    float acc[4][4][4] = {};
    const int a_row = wm + (lane & 15);
    const int a_kof = (lane >> 4) * 8;
    const int bt_k  = lane & 15;
    const int bt_n  = ((lane >> 4) & 1) * 8;

    loadStage(0, 0); CP_COMMIT();
    for (int s = 0; s < 6; s++) {
        if (s + 1 < 6) { loadStage(s + 1, (s + 1) & 1); CP_COMMIT(); CP_WAIT(1); }
        else CP_WAIT(0);
        __syncthreads();
        const uint32_t abase = aB + (s & 1) * TILE_B;
        const uint32_t bbase = bB + (s & 1) * TILE_B;
#pragma unroll
        for (int ks = 0; ks < 4; ks++) {
            uint32_t af[4][4];
#pragma unroll
            for (int mi = 0; mi < 4; mi++)
                ldsm_x4(af[mi], abase + SW128((a_row + mi * 16) * 128 + (ks * 16 + a_kof) * 2));
            uint32_t bt[2][4];
#pragma unroll
            for (int g = 0; g < 2; g++)
                ldsm_x4t(bt[g], bbase + SWZ256((ks * 16 + bt_k) * 256 + (wn + g * 16 + bt_n) * 2));
#pragma unroll
            for (int mi = 0; mi < 4; mi++)
#pragma unroll
                for (int g = 0; g < 2; g++) {
                    mma_16816(acc[mi][g * 2 + 0], af[mi], &bt[g][0]);
                    mma_16816(acc[mi][g * 2 + 1], af[mi], &bt[g][2]);
                }
        }
        __syncthreads();
    }

    const int er = p0 + wm + (lane >> 2);
    const int ec = e0 + wn + (lane & 3) * 2;
#pragma unroll
    for (int mi = 0; mi < 4; mi++)
#pragma unroll
        for (int ni = 0; ni < 4; ni++) {
            int col = ec + ni * 8;
#pragma unroll
            for (int half = 0; half < 2; half++) {
                int row = er + mi * 16 + half * 8;
                float g0 = __bfloat162float(g_h_bf[(size_t)row * TWOH + HHID + col + 0]);
                float g1 = __bfloat162float(g_h_bf[(size_t)row * TWOH + HHID + col + 1]);
                st_bf2(g_gated_bf + (size_t)row * HHID + col,
                       g0 * acc[mi][ni][half * 2 + 0], g1 * acc[mi][ni][half * 2 + 1]);
            }
        }
}

// =================== transpose + fp32->bf16 convert ==========
__global__ void transpose_bf_kernel(const float* __restrict__ in,
                                    __nv_bfloat16* __restrict__ out, int R, int Cc) {
    __shared__ float t[32][33];
    int c0 = blockIdx.x * 32, r0 = blockIdx.y * 32;
    int x = threadIdx.x, y = threadIdx.y;
#pragma unroll
    for (int i = 0; i < 32; i += 8)
        t[y + i][x] = in[(size_t)(r0 + y + i) * Cc + c0 + x];
    __syncthreads();
#pragma unroll
    for (int i = 0; i < 32; i += 8)
        out[(size_t)(c0 + y + i) * R + r0 + x] = __float2bfloat16(t[x][y + i]);
}

// ------- RoPE tables: grid (64 j, 8 n-chunks); one fp64 pow per block -------
__global__ void rope_table_kernel() {
    int j = blockIdx.x;
    float invf = (float)pow(10000.0, (double)j / 64.0);
    int n = blockIdx.y * 256 + threadIdx.x;
    float ang = (float)n * invf;
    g_sin[n*64 + j] = sinf(ang);
    g_cos[n*64 + j] = cosf(ang);
}

// ---------------- LayerNorm (emits bf16 A operand) ----------------
__global__ void ln_kernel(const float* __restrict__ x,
                          const float* __restrict__ gam,
                          const float* __restrict__ bet) {
    int row = blockIdx.x, t = threadIdx.x;
    const float* xr = x + (size_t)row * DD;
    float v[4]; float s = 0.f;
#pragma unroll
    for (int c = 0; c < 4; c++) { v[c] = xr[t + 256*c]; s += v[c]; }
    __shared__ float red[8];
    __shared__ float bcast;
    int lane = t & 31, w = t >> 5;
#pragma unroll
    for (int o = 16; o; o >>= 1) s += __shfl_xor_sync(~0u, s, o);
    if (lane == 0) red[w] = s;
    __syncthreads();
    if (t == 0) { float tot = 0; for (int i = 0; i < 8; i++) tot += red[i]; bcast = tot / DD; }
    __syncthreads();
    float mu = bcast;
    float s2 = 0.f;
#pragma unroll
    for (int c = 0; c < 4; c++) { float d = v[c] - mu; s2 += d * d; }
#pragma unroll
    for (int o = 16; o; o >>= 1) s2 += __shfl_xor_sync(~0u, s2, o);
    __syncthreads();
    if (lane == 0) red[w] = s2;
    __syncthreads();
    if (t == 0) { float tot = 0; for (int i = 0; i < 8; i++) tot += red[i];
                  bcast = 1.0f / sqrtf(tot / DD + 1e-5f); }
    __syncthreads();
    float rstd = bcast;
    __nv_bfloat16* out = g_normed_bf + (size_t)row * DD;
#pragma unroll
    for (int c = 0; c < 4; c++) {
        int d = t + 256*c;
        out[d] = __float2bfloat16((v[c] - mu) * rstd * gam[d] + bet[d]);
    }
}

// -------- OffsetScale + RoPE: all four heads -> bf16 --------
__global__ void rope_apply_kernel(const float* __restrict__ gamma,
                                  const float* __restrict__ beta) {
    int tid = threadIdx.x;
    int tok = blockIdx.x * 4 + (tid >> 6);
    int j   = tid & 63;
    int n   = tok & (SEQ - 1);
    int b   = tok >> 11;
    float v1 = g_qk[(size_t)tok * QKD + j];
    float v2 = g_qk[(size_t)tok * QKD + j + 64];
    float sn = g_sin[n*64 + j], cs = g_cos[n*64 + j];
    {
        float a1 = v1 * gamma[0*QKD + j]      + beta[0*QKD + j];
        float a2 = v2 * gamma[0*QKD + j + 64] + beta[0*QKD + j + 64];
        g_quadq_bf[(size_t)tok * QKD + j]      = __float2bfloat16(a1 * cs - a2 * sn);
        g_quadq_bf[(size_t)tok * QKD + j + 64] = __float2bfloat16(a2 * cs + a1 * sn);
    }
    {
        float a1 = v1 * gamma[2*QKD + j]      + beta[2*QKD + j];
        float a2 = v2 * gamma[2*QKD + j + 64] + beta[2*QKD + j + 64];
        g_quadk_bf[(size_t)tok * QKD + j]      = __float2bfloat16(a1 * cs - a2 * sn);
        g_quadk_bf[(size_t)tok * QKD + j + 64] = __float2bfloat16(a2 * cs + a1 * sn);
    }
    {
        float a1 = v1 * gamma[1*QKD + j]      + beta[1*QKD + j];
        float a2 = v2 * gamma[1*QKD + j + 64] + beta[1*QKD + j + 64];
        g_linq_bf[(size_t)tok * QKD + j]      = __float2bfloat16(a1 * cs - a2 * sn);
        g_linq_bf[(size_t)tok * QKD + j + 64] = __float2bfloat16(a2 * cs + a1 * sn);
    }
    {
        float a1 = v1 * gamma[3*QKD + j]      + beta[3*QKD + j];
        float a2 = v2 * gamma[3*QKD + j + 64] + beta[3*QKD + j + 64];
        __nv_bfloat16* base = g_linkT_bf + (size_t)b * QKD * SEQ;
        base[(size_t)j * SEQ + n]        = __float2bfloat16(a1 * cs - a2 * sn);
        base[(size_t)(j + 64) * SEQ + n] = __float2bfloat16(a2 * cs + a1 * sn);
    }
}

// ---------------------------------------------------------------------------
extern "C" void kernel_launch(void* const* d_in, const int* in_sizes, int n_in,
                              void* d_out, int out_size) {
    const float* x        = (const float*)d_in[0];
    const float* ln_g     = (const float*)d_in[1];
    const float* ln_b     = (const float*)d_in[2];
    const float* W_hidden = (const float*)d_in[3];
    const float* b_hidden = (const float*)d_in[4];
    const float* W_qk     = (const float*)d_in[5];
    const float* b_qk     = (const float*)d_in[6];
    const float* os_gamma = (const float*)d_in[7];
    const float* os_beta  = (const float*)d_in[8];
    const float* W_out    = (const float*)d_in[9];
    const float* b_out    = (const float*)d_in[10];
    float* out = (float*)d_out;

    __nv_bfloat16 *normed_bf, *whT, *wqkT, *woT, *gated_bf, *h_bf;
    float *qk;
    cudaGetSymbolAddress((void**)&normed_bf, g_normed_bf);
    cudaGetSymbolAddress((void**)&whT,  g_whT);
    cudaGetSymbolAddress((void**)&wqkT, g_wqkT);
    cudaGetSymbolAddress((void**)&woT,  g_woT);
    cudaGetSymbolAddress((void**)&gated_bf, g_gated_bf);
    cudaGetSymbolAddress((void**)&h_bf, g_h_bf);
    cudaGetSymbolAddress((void**)&qk, g_qk);

    const int SMEM_BIG   = 3 * (16384 + 32768);   // 147456 (N_CTA=256)
    const int SMEM_SMALL = 3 * (16384 + 16384);   // 98304  (N_CTA=128)
    const int SMEM_ATTN  = 4 * 128 * 128;         // 64 KB
    const int SMEM_LK    = 2 * 16384 + 2 * 8192;  // 48 KB
    cudaFuncSetAttribute(mm_bf16_kernel<256,1024,true,false,true>,
                         cudaFuncAttributeMaxDynamicSharedMemorySize, SMEM_BIG);
    cudaFuncSetAttribute(mm_bf16_kernel<128,1024,true,false,false>,
                         cudaFuncAttributeMaxDynamicSharedMemorySize, SMEM_SMALL);
    cudaFuncSetAttribute(mm_bf16_kernel<256,2048,false,true,false>,
                         cudaFuncAttributeMaxDynamicSharedMemorySize, SMEM_BIG);
    cudaFuncSetAttribute(attn_hmma_kernel,
                         cudaFuncAttributeMaxDynamicSharedMemorySize, SMEM_ATTN);
    cudaFuncSetAttribute(linkv_hmma_kernel,
                         cudaFuncAttributeMaxDynamicSharedMemorySize, SMEM_LK);
    cudaFuncSetAttribute(fused_hmma_kernel,
                         cudaFuncAttributeMaxDynamicSharedMemorySize, SMEM_ATTN);

    transpose_bf_kernel<<<dim3(TWOH/32, DD/32), dim3(32,8)>>>(W_hidden, whT, DD, TWOH);
    transpose_bf_kernel<<<dim3(QKD/32,  DD/32), dim3(32,8)>>>(W_qk,  wqkT, DD, QKD);
    transpose_bf_kernel<<<dim3(DD/32, HHID/32), dim3(32,8)>>>(W_out, woT,  HHID, DD);

    rope_table_kernel<<<dim3(64, SEQ/256), 256>>>();
    ln_kernel<<<MROWS, 256>>>(x, ln_g, ln_b);

    // h = silu(normed @ W_hidden + b) -> bf16 [8192, 4096]
    mm_bf16_kernel<256,1024,true,false,true><<<dim3(TWOH/256, MROWS/128), 256, SMEM_BIG>>>(
        normed_bf, whT, b_hidden, nullptr, nullptr, h_bf, TWOH);
    // qk = silu(normed @ W_qk + b) -> fp32 [8192, 128]
    mm_bf16_kernel<128,1024,true,false,false><<<dim3(QKD/128, MROWS/128), 256, SMEM_SMALL>>>(
        normed_bf, wqkT, b_qk, nullptr, qk, nullptr, QKD);

    rope_apply_kernel<<<MROWS/4, 256>>>(os_gamma, os_beta);
    attn_hmma_kernel<<<dim3(GG/128, GG/128, NGRP), 256, SMEM_ATTN>>>();
    linkv_hmma_kernel<<<dim3(HHID/64, BB), 256, SMEM_LK>>>();
    fused_hmma_kernel<<<dim3(HHID/128, MROWS/128), 256, SMEM_ATTN>>>();

    // out = gated @ W_out + b_out + x  [8192, 1024]
    mm_bf16_kernel<256,2048,false,true,false><<<dim3(DD/256, MROWS/128), 256, SMEM_BIG>>>(
        gated_bf, woT, b_out, x, out, nullptr, DD);
}

// round 12
// speedup vs baseline: 6.6114x; 1.0454x over previous
#include <cuda_runtime.h>
#include <cuda_bf16.h>
#include <math.h>
#include <cstdint>

// Problem constants
#define BB   4
#define SEQ  2048
#define DD   1024
#define GG   256
#define QKD  128
#define HHID 2048
#define MROWS (BB*SEQ)        // 8192
#define NGRP  (MROWS/GG)      // 32
#define TWOH  (2*HHID)        // 4096

// -------- device scratch (no cudaMalloc allowed) --------
__device__ __nv_bfloat16 g_normed_bf[(size_t)MROWS*DD];    // 16 MB
__device__ __nv_bfloat16 g_h_bf[(size_t)MROWS*TWOH];       // 64 MB (v | gate)
__device__ float g_qk[(size_t)MROWS*QKD];                  // 4 MB
__device__ __nv_bfloat16 g_quadq_bf[(size_t)MROWS*QKD];    // 2 MB
__device__ __nv_bfloat16 g_quadk_bf[(size_t)MROWS*QKD];    // 2 MB
__device__ __nv_bfloat16 g_linq_bf[(size_t)MROWS*QKD];     // 2 MB
__device__ __nv_bfloat16 g_linkT_bf[(size_t)BB*QKD*SEQ];   // 2 MB  lin_k^T [b][d][n]
__device__ __nv_bfloat16 g_attn_bf[(size_t)NGRP*GG*GG];    // 4 MB
__device__ __nv_bfloat16 g_linkv_bf[(size_t)BB*QKD*HHID];  // 2 MB
__device__ __nv_bfloat16 g_gated_bf[(size_t)MROWS*HHID];   // 32 MB
__device__ __nv_bfloat16 g_whT[(size_t)TWOH*DD];           // 8 MB
__device__ __nv_bfloat16 g_wqkT[(size_t)QKD*DD];           // 0.25 MB
__device__ __nv_bfloat16 g_woT[(size_t)DD*HHID];           // 4 MB
__device__ float g_sin[SEQ*64];
__device__ float g_cos[SEQ*64];

// =================== PTX helpers (arch-portable: sm_80+ subset) ===================
__device__ __forceinline__ uint32_t smem_u32(const void* p) {
    uint32_t a;
    asm("{ .reg .u64 t; cvta.to.shared.u64 t, %1; cvt.u32.u64 %0, t; }" : "=r"(a) : "l"(p));
    return a;
}
#define SW128(o) ((o) ^ (((o) >> 3) & 0x70))   // 128B rows
#define SWZ256(o) ((o) ^ (((o) >> 4) & 0x70))  // 256B rows

__device__ __forceinline__ void cpa16(uint32_t dst, const void* src) {
    asm volatile("cp.async.cg.shared.global [%0], [%1], 16;" :: "r"(dst), "l"(src));
}
#define CP_COMMIT() asm volatile("cp.async.commit_group;" ::: "memory")
#define CP_WAIT(n)  asm volatile("cp.async.wait_group %0;" :: "n"(n) : "memory")

__device__ __forceinline__ void ldsm_x4(uint32_t* r, uint32_t addr) {
    asm volatile("ldmatrix.sync.aligned.m8n8.x4.shared.b16 {%0,%1,%2,%3}, [%4];"
                 : "=r"(r[0]), "=r"(r[1]), "=r"(r[2]), "=r"(r[3]) : "r"(addr));
}
__device__ __forceinline__ void ldsm_x2(uint32_t* r, uint32_t addr) {
    asm volatile("ldmatrix.sync.aligned.m8n8.x2.shared.b16 {%0,%1}, [%2];"
                 : "=r"(r[0]), "=r"(r[1]) : "r"(addr));
}
__device__ __forceinline__ void ldsm_x4t(uint32_t* r, uint32_t addr) {
    asm volatile("ldmatrix.sync.aligned.m8n8.x4.trans.shared.b16 {%0,%1,%2,%3}, [%4];"
                 : "=r"(r[0]), "=r"(r[1]), "=r"(r[2]), "=r"(r[3]) : "r"(addr));
}
__device__ __forceinline__ void mma_16816(float* c, const uint32_t* a, const uint32_t* b) {
    asm volatile(
        "mma.sync.aligned.m16n8k16.row.col.f32.bf16.bf16.f32 "
        "{%0,%1,%2,%3}, {%4,%5,%6,%7}, {%8,%9}, {%0,%1,%2,%3};"
        : "+f"(c[0]), "+f"(c[1]), "+f"(c[2]), "+f"(c[3])
        : "r"(a[0]), "r"(a[1]), "r"(a[2]), "r"(a[3]), "r"(b[0]), "r"(b[1]));
}
__device__ __forceinline__ void st_bf2(__nv_bfloat16* p, float a, float b) {
    *(__nv_bfloat162*)p = __floats2bfloat162_rn(a, b);
}

// ====== bf16 tensor-core GEMM: C[M,N] = A[M,K] @ Bt[N,K]^T ======
// CTA tile 128 x N_CTA, 8 warps (2 x 4), warp tile 64 x (N_CTA/4).
// 4-stage cp.async ring.
template<int N_CTA, int K_TOT, bool SILU_, bool RESID_, bool OUTBF_>
__global__ void __launch_bounds__(256, 1)
mm_bf16_kernel(const __nv_bfloat16* __restrict__ A,
               const __nv_bfloat16* __restrict__ Bt,
               const float* __restrict__ bias,
               const float* __restrict__ resid,
               float* __restrict__ Cf, __nv_bfloat16* __restrict__ Cb, int ldC)
{
    constexpr int STAGES = K_TOT / 64;
    constexpr int A_B    = 128 * 128;       // 16 KB
    constexpr int B_B    = N_CTA * 128;     // 16/32 KB
    constexpr int NI     = N_CTA / 32;
    constexpr int NBCH   = N_CTA / 32;
    extern __shared__ char smem[];
    const uint32_t aB = smem_u32(smem);
    const uint32_t bB = aB + 4 * A_B;

    const int tid = threadIdx.x, wid = tid >> 5, lane = tid & 31;
    const int m0 = blockIdx.y * 128, n0 = blockIdx.x * N_CTA;
    const int wm = (wid >> 2) * 64;
    const int wn = (wid & 3) * (N_CTA / 4);

    auto loadA = [&](int s, int buf) {
        uint32_t base = aB + buf * A_B;
        const __nv_bfloat16* src = A + (size_t)m0 * K_TOT + s * 64;
#pragma unroll
        for (int i = 0; i < 4; i++) {
            int c = tid + i * 256;
            int row = c >> 3, col = c & 7;
            cpa16(base + SW128(row * 128 + col * 16), src + (size_t)row * K_TOT + col * 8);
        }
    };
    auto loadB = [&](int s, int buf) {
        uint32_t base = bB + buf * B_B;
        const __nv_bfloat16* src = Bt + (size_t)n0 * K_TOT + s * 64;
#pragma unroll
        for (int i = 0; i < NBCH; i++) {
            int c = tid + i * 256;
            int row = c >> 3, col = c & 7;
            cpa16(base + SW128(row * 128 + col * 16), src + (size_t)row * K_TOT + col * 8);
        }
    };

    float acc[4][NI][4] = {};
    const int a_row = wm + (lane & 15);
    const int a_kof = (lane >> 4) * 8;
    const int b_row = wn + (lane & 7);
    const int b_kof = ((lane >> 3) & 1) * 8;

    loadA(0, 0); loadB(0, 0); CP_COMMIT();
    loadA(1, 1); loadB(1, 1); CP_COMMIT();
    loadA(2, 2); loadB(2, 2); CP_COMMIT();

    for (int s = 0; s < STAGES; s++) {
        if (s + 3 < STAGES) {
            loadA(s + 3, (s + 3) & 3); loadB(s + 3, (s + 3) & 3);
            CP_COMMIT(); CP_WAIT(3);
        } else if (s + 2 < STAGES) CP_WAIT(2);
        else if (s + 1 < STAGES) CP_WAIT(1);
        else CP_WAIT(0);
        __syncthreads();
        const uint32_t abase = aB + (s & 3) * A_B;
        const uint32_t bbase = bB + (s & 3) * B_B;
#pragma unroll
        for (int ks = 0; ks < 4; ks++) {
            uint32_t af[4][4];
#pragma unroll
            for (int mi = 0; mi < 4; mi++)
                ldsm_x4(af[mi], abase + SW128((a_row + mi * 16) * 128 + (ks * 16 + a_kof) * 2));
            uint32_t bf[NI][2];
#pragma unroll
            for (int ni = 0; ni < NI; ni++)
                ldsm_x2(bf[ni], bbase + SW128((b_row + ni * 8) * 128 + (ks * 16 + b_kof) * 2));
#pragma unroll
            for (int mi = 0; mi < 4; mi++)
#pragma unroll
                for (int ni = 0; ni < NI; ni++)
                    mma_16816(acc[mi][ni], af[mi], bf[ni]);
        }
        __syncthreads();
    }

    const int er = m0 + wm + (lane >> 2);
    const int ec = n0 + wn + (lane & 3) * 2;
#pragma unroll
    for (int mi = 0; mi < 4; mi++)
#pragma unroll
        for (int ni = 0; ni < NI; ni++) {
            int col = ec + ni * 8;
#pragma unroll
            for (int half = 0; half < 2; half++) {
                int row = er + mi * 16 + half * 8;
                float v0 = acc[mi][ni][half * 2 + 0] + bias[col + 0];
                float v1 = acc[mi][ni][half * 2 + 1] + bias[col + 1];
                if (SILU_) { v0 = v0 / (1.0f + expf(-v0)); v1 = v1 / (1.0f + expf(-v1)); }
                if (RESID_) {
                    v0 += resid[(size_t)row * ldC + col + 0];
                    v1 += resid[(size_t)row * ldC + col + 1];
                }
                if (OUTBF_) st_bf2(Cb + (size_t)row * ldC + col, v0, v1);
                else { float2 o; o.x = v0; o.y = v1; *(float2*)(Cf + (size_t)row * ldC + col) = o; }
            }
        }
}

// ====== attn HMMA: attn = relu(quad_q @ quad_k^T / g)^2 -> bf16  (128x128 tile) ======
__global__ void __launch_bounds__(256)
attn_hmma_kernel()
{
    constexpr int TILE_B = 128 * 128;
    extern __shared__ char smem[];
    const uint32_t aB = smem_u32(smem);
    const uint32_t bB = aB + 2 * TILE_B;

    const int tid = threadIdx.x, wid = tid >> 5, lane = tid & 31;
    const int gid = blockIdx.z;
    const int i0 = blockIdx.y * 128, j0 = blockIdx.x * 128;
    const int wm = (wid >> 2) * 64;
    const int wn = (wid & 3) * 32;

    const __nv_bfloat16* Aq = g_quadq_bf + ((size_t)gid * GG + i0) * QKD;
    const __nv_bfloat16* Bk = g_quadk_bf + ((size_t)gid * GG + j0) * QKD;

    auto loadT = [&](const __nv_bfloat16* src, uint32_t base, int s) {
        const __nv_bfloat16* p = src + s * 64;
#pragma unroll
        for (int i = 0; i < 4; i++) {
            int c = tid + i * 256;
            int row = c >> 3, col = c & 7;
            cpa16(base + SW128(row * 128 + col * 16), p + (size_t)row * QKD + col * 8);
        }
    };

    float acc[4][4][4] = {};
    const int a_row = wm + (lane & 15);
    const int a_kof = (lane >> 4) * 8;
    const int b_row = wn + (lane & 7);
    const int b_kof = ((lane >> 3) & 1) * 8;

    loadT(Aq, aB, 0); loadT(Bk, bB, 0); CP_COMMIT();
    for (int s = 0; s < 2; s++) {
        if (s + 1 < 2) {
            loadT(Aq, aB + TILE_B, 1); loadT(Bk, bB + TILE_B, 1);
            CP_COMMIT(); CP_WAIT(1);
        } else CP_WAIT(0);
        __syncthreads();
        const uint32_t abase = aB + s * TILE_B;
        const uint32_t bbase = bB + s * TILE_B;
#pragma unroll
        for (int ks = 0; ks < 4; ks++) {
            uint32_t af[4][4];
#pragma unroll
            for (int mi = 0; mi < 4; mi++)
                ldsm_x4(af[mi], abase + SW128((a_row + mi * 16) * 128 + (ks * 16 + a_kof) * 2));
            uint32_t bf[4][2];
#pragma unroll
            for (int ni = 0; ni < 4; ni++)
                ldsm_x2(bf[ni], bbase + SW128((b_row + ni * 8) * 128 + (ks * 16 + b_kof) * 2));
#pragma unroll
            for (int mi = 0; mi < 4; mi++)
#pragma unroll
                for (int ni = 0; ni < 4; ni++)
                    mma_16816(acc[mi][ni], af[mi], bf[ni]);
        }
        __syncthreads();
    }

    __nv_bfloat16* Cp = g_attn_bf + (size_t)gid * GG * GG;
    const int er = i0 + wm + (lane >> 2);
    const int ec = j0 + wn + (lane & 3) * 2;
#pragma unroll
    for (int mi = 0; mi < 4; mi++)
#pragma unroll
        for (int ni = 0; ni < 4; ni++) {
            int col = ec + ni * 8;
#pragma unroll
            for (int half = 0; half < 2; half++) {
                int row = er + mi * 16 + half * 8;
                float s0 = fmaxf(acc[mi][ni][half * 2 + 0] * (1.0f / GG), 0.0f);
                float s1 = fmaxf(acc[mi][ni][half * 2 + 1] * (1.0f / GG), 0.0f);
                st_bf2(Cp + (size_t)row * GG + col, s0 * s0, s1 * s1);
            }
        }
}

// ====== linkv HMMA: linkv[b,d,e] = sum_n lin_kT[b,d,n] * v[b,n,e] / SEQ ======
__global__ void __launch_bounds__(256)
linkv_hmma_kernel()
{
    constexpr int A_B = 128 * 128;
    constexpr int B_B = 64 * 128;
    extern __shared__ char smem[];
    const uint32_t aB = smem_u32(smem);
    const uint32_t bB = aB + 2 * A_B;

    const int tid = threadIdx.x, wid = tid >> 5, lane = tid & 31;
    const int b  = blockIdx.y;
    const int e0 = blockIdx.x * 64;
    const int wm = (wid & 3) * 32;
    const int wn = (wid >> 2) * 32;

    auto loadA = [&](int s, int buf) {
        uint32_t base = aB + buf * A_B;
        const __nv_bfloat16* src = g_linkT_bf + (size_t)b * QKD * SEQ + s * 64;
#pragma unroll
        for (int i = 0; i < 4; i++) {
            int c = tid + i * 256;
            int row = c >> 3, col = c & 7;
            cpa16(base + SW128(row * 128 + col * 16), src + (size_t)row * SEQ + col * 8);
        }
    };
    auto loadB = [&](int s, int buf) {
        uint32_t base = bB + buf * B_B;
        const __nv_bfloat16* src = g_h_bf + ((size_t)(b * SEQ + s * 64)) * TWOH + e0;
#pragma unroll
        for (int i = 0; i < 2; i++) {
            int c = tid + i * 256;
            int row = c >> 3, col = c & 7;
            cpa16(base + SW128(row * 128 + col * 16), src + (size_t)row * TWOH + col * 8);
        }
    };

    float acc[2][4][4] = {};
    const int a_row = wm + (lane & 15);
    const int a_kof = (lane >> 4) * 8;
    const int bt_k  = lane & 15;
    const int bt_n  = ((lane >> 4) & 1) * 8;

    loadA(0, 0); loadB(0, 0); CP_COMMIT();
    for (int s = 0; s < SEQ / 64; s++) {
        if (s + 1 < SEQ / 64) {
            loadA(s + 1, (s + 1) & 1); loadB(s + 1, (s + 1) & 1);
            CP_COMMIT(); CP_WAIT(1);
        } else CP_WAIT(0);
        __syncthreads();
        const uint32_t abase = aB + (s & 1) * A_B;
        const uint32_t bbase = bB + (s & 1) * B_B;
#pragma unroll
        for (int ks = 0; ks < 4; ks++) {
            uint32_t af[2][4];
#pragma unroll
            for (int mi = 0; mi < 2; mi++)
                ldsm_x4(af[mi], abase + SW128((a_row + mi * 16) * 128 + (ks * 16 + a_kof) * 2));
            uint32_t bt[2][4];
#pragma unroll
            for (int g = 0; g < 2; g++)
                ldsm_x4t(bt[g], bbase + SW128((ks * 16 + bt_k) * 128 + (wn + g * 16 + bt_n) * 2));
#pragma unroll
            for (int mi = 0; mi < 2; mi++)
#pragma unroll
                for (int g = 0; g < 2; g++) {
                    mma_16816(acc[mi][g * 2 + 0], af[mi], &bt[g][0]);
                    mma_16816(acc[mi][g * 2 + 1], af[mi], &bt[g][2]);
                }
        }
        __syncthreads();
    }

    __nv_bfloat16* Cp = g_linkv_bf + (size_t)b * QKD * HHID;
    const int er = wm + (lane >> 2);
    const int ec = e0 + wn + (lane & 3) * 2;
#pragma unroll
    for (int mi = 0; mi < 2; mi++)
#pragma unroll
        for (int ni = 0; ni < 4; ni++) {
            int col = ec + ni * 8;
#pragma unroll
            for (int half = 0; half < 2; half++) {
                int row = er + mi * 16 + half * 8;
                st_bf2(Cp + (size_t)row * HHID + col,
                       acc[mi][ni][half * 2 + 0] * (1.0f / SEQ),
                       acc[mi][ni][half * 2 + 1] * (1.0f / SEQ));
            }
        }
}

// ====== fused HMMA: gated = gate * (attn@v + lin_q@lin_kv)  (128p x 128e tile) ======
__global__ void __launch_bounds__(256)
fused_hmma_kernel()
{
    constexpr int TILE_B = 128 * 128;
    extern __shared__ char smem[];
    const uint32_t aB = smem_u32(smem);
    const uint32_t bB = aB + 2 * TILE_B;

    const int tid = threadIdx.x, wid = tid >> 5, lane = tid & 31;
    const int p0 = blockIdx.y * 128, e0 = blockIdx.x * 128;
    const int gid = p0 >> 8, b = p0 >> 11, i0 = p0 & 255;
    const int wm = (wid >> 2) * 64;
    const int wn = (wid & 3) * 32;

    auto loadStage = [&](int s, int buf) {
        uint32_t abase = aB + buf * TILE_B;
        uint32_t bbase = bB + buf * TILE_B;
        if (s < 4) {
            const __nv_bfloat16* asrc = g_attn_bf + (size_t)gid * GG * GG + (size_t)i0 * GG + s * 64;
#pragma unroll
            for (int i = 0; i < 4; i++) {
                int c = tid + i * 256;
                int row = c >> 3, col = c & 7;
                cpa16(abase + SW128(row * 128 + col * 16), asrc + (size_t)row * GG + col * 8);
            }
            const __nv_bfloat16* bsrc = g_h_bf + ((size_t)(gid * GG + s * 64)) * TWOH + e0;
#pragma unroll
            for (int i = 0; i < 4; i++) {
                int c = tid + i * 256;
                int row = c >> 4, col = c & 15;
                cpa16(bbase + SWZ256(row * 256 + col * 16), bsrc + (size_t)row * TWOH + col * 8);
            }
        } else {
            int s2 = s - 4;
            const __nv_bfloat16* asrc = g_linq_bf + (size_t)p0 * QKD + s2 * 64;
#pragma unroll
            for (int i = 0; i < 4; i++) {
                int c = tid + i * 256;
                int row = c >> 3, col = c & 7;
                cpa16(abase + SW128(row * 128 + col * 16), asrc + (size_t)row * QKD + col * 8);
            }
            const __nv_bfloat16* bsrc = g_linkv_bf + (size_t)b * QKD * HHID + (size_t)(s2 * 64) * HHID + e0;
#pragma unroll
            for (int i = 0; i < 4; i++) {
                int c = tid + i * 256;
                int row = c >> 4, col = c & 15;
                cpa16(bbase + SWZ256(row * 256 + col * 16), bsrc + (size_t)row * TWOH / 2 + col * 8);
            }
        }
    };

    float acc[4][4][4] = {};
    const int a_row = wm + (lane & 15);
    const int a_kof = (lane >> 4) * 8;
    const int bt_k  = lane & 15;
    const int bt_n  = ((lane >> 4) & 1) * 8;

    loadStage(0, 0); CP_COMMIT();
    for (int s = 0; s < 6; s++) {
        if (s + 1 < 6) { loadStage(s + 1, (s + 1) & 1); CP_COMMIT(); CP_WAIT(1); }
        else CP_WAIT(0);
        __syncthreads();
        const uint32_t abase = aB + (s & 1) * TILE_B;
        const uint32_t bbase = bB + (s & 1) * TILE_B;
#pragma unroll
        for (int ks = 0; ks < 4; ks++) {
            uint32_t af[4][4];
#pragma unroll
            for (int mi = 0; mi < 4; mi++)
                ldsm_x4(af[mi], abase + SW128((a_row + mi * 16) * 128 + (ks * 16 + a_kof) * 2));
            uint32_t bt[2][4];
#pragma unroll
            for (int g = 0; g < 2; g++)
                ldsm_x4t(bt[g], bbase + SWZ256((ks * 16 + bt_k) * 256 + (wn + g * 16 + bt_n) * 2));
#pragma unroll
            for (int mi = 0; mi < 4; mi++)
#pragma unroll
                for (int g = 0; g < 2; g++) {
                    mma_16816(acc[mi][g * 2 + 0], af[mi], &bt[g][0]);
                    mma_16816(acc[mi][g * 2 + 1], af[mi], &bt[g][2]);
                }
        }
        __syncthreads();
    }

    const int er = p0 + wm + (lane >> 2);
    const int ec = e0 + wn + (lane & 3) * 2;
#pragma unroll
    for (int mi = 0; mi < 4; mi++)
#pragma unroll
        for (int ni = 0; ni < 4; ni++) {
            int col = ec + ni * 8;
#pragma unroll
            for (int half = 0; half < 2; half++) {
                int row = er + mi * 16 + half * 8;
                float g0 = __bfloat162float(g_h_bf[(size_t)row * TWOH + HHID + col + 0]);
                float g1 = __bfloat162float(g_h_bf[(size_t)row * TWOH + HHID + col + 1]);
                st_bf2(g_gated_bf + (size_t)row * HHID + col,
                       g0 * acc[mi][ni][half * 2 + 0], g1 * acc[mi][ni][half * 2 + 1]);
            }
        }
}

// =================== transpose + fp32->bf16 convert ==========
__global__ void transpose_bf_kernel(const float* __restrict__ in,
                                    __nv_bfloat16* __restrict__ out, int R, int Cc) {
    __shared__ float t[32][33];
    int c0 = blockIdx.x * 32, r0 = blockIdx.y * 32;
    int x = threadIdx.x, y = threadIdx.y;
#pragma unroll
    for (int i = 0; i < 32; i += 8)
        t[y + i][x] = in[(size_t)(r0 + y + i) * Cc + c0 + x];
    __syncthreads();
#pragma unroll
    for (int i = 0; i < 32; i += 8)
        out[(size_t)(c0 + y + i) * R + r0 + x] = __float2bfloat16(t[x][y + i]);
}

// ------- RoPE tables: one fp64 pow per BLOCK (thread 0), broadcast via smem -------
__global__ void rope_table_kernel() {
    __shared__ float sf;
    int j = blockIdx.x;
    if (threadIdx.x == 0) sf = (float)pow(10000.0, (double)j / 64.0);
    __syncthreads();
    float invf = sf;
    int n = blockIdx.y * 256 + threadIdx.x;
    float ang = (float)n * invf;
    g_sin[n*64 + j] = sinf(ang);
    g_cos[n*64 + j] = cosf(ang);
}

// ---------------- LayerNorm (emits bf16 A operand) ----------------
__global__ void ln_kernel(const float* __restrict__ x,
                          const float* __restrict__ gam,
                          const float* __restrict__ bet) {
    int row = blockIdx.x, t = threadIdx.x;
    const float* xr = x + (size_t)row * DD;
    float v[4]; float s = 0.f;
#pragma unroll
    for (int c = 0; c < 4; c++) { v[c] = xr[t + 256*c]; s += v[c]; }
    __shared__ float red[8];
    __shared__ float bcast;
    int lane = t & 31, w = t >> 5;
#pragma unroll
    for (int o = 16; o; o >>= 1) s += __shfl_xor_sync(~0u, s, o);
    if (lane == 0) red[w] = s;
    __syncthreads();
    if (t == 0) { float tot = 0; for (int i = 0; i < 8; i++) tot += red[i]; bcast = tot / DD; }
    __syncthreads();
    float mu = bcast;
    float s2 = 0.f;
#pragma unroll
    for (int c = 0; c < 4; c++) { float d = v[c] - mu; s2 += d * d; }
#pragma unroll
    for (int o = 16; o; o >>= 1) s2 += __shfl_xor_sync(~0u, s2, o);
    __syncthreads();
    if (lane == 0) red[w] = s2;
    __syncthreads();
    if (t == 0) { float tot = 0; for (int i = 0; i < 8; i++) tot += red[i];
                  bcast = 1.0f / sqrtf(tot / DD + 1e-5f); }
    __syncthreads();
    float rstd = bcast;
    __nv_bfloat16* out = g_normed_bf + (size_t)row * DD;
#pragma unroll
    for (int c = 0; c < 4; c++) {
        int d = t + 256*c;
        out[d] = __float2bfloat16((v[c] - mu) * rstd * gam[d] + bet[d]);
    }
}

// -------- OffsetScale + RoPE: all four heads -> bf16 --------
__global__ void rope_apply_kernel(const float* __restrict__ gamma,
                                  const float* __restrict__ beta) {
    int tid = threadIdx.x;
    int tok = blockIdx.x * 4 + (tid >> 6);
    int j   = tid & 63;
    int n   = tok & (SEQ - 1);
    int b   = tok >> 11;
    float v1 = g_qk[(size_t)tok * QKD + j];
    float v2 = g_qk[(size_t)tok * QKD + j + 64];
    float sn = g_sin[n*64 + j], cs = g_cos[n*64 + j];
    {
        float a1 = v1 * gamma[0*QKD + j]      + beta[0*QKD + j];
        float a2 = v2 * gamma[0*QKD + j + 64] + beta[0*QKD + j + 64];
        g_quadq_bf[(size_t)tok * QKD + j]      = __float2bfloat16(a1 * cs - a2 * sn);
        g_quadq_bf[(size_t)tok * QKD + j + 64] = __float2bfloat16(a2 * cs + a1 * sn);
    }
    {
        float a1 = v1 * gamma[2*QKD + j]      + beta[2*QKD + j];
        float a2 = v2 * gamma[2*QKD + j + 64] + beta[2*QKD + j + 64];
        g_quadk_bf[(size_t)tok * QKD + j]      = __float2bfloat16(a1 * cs - a2 * sn);
        g_quadk_bf[(size_t)tok * QKD + j + 64] = __float2bfloat16(a2 * cs + a1 * sn);
    }
    {
        float a1 = v1 * gamma[1*QKD + j]      + beta[1*QKD + j];
        float a2 = v2 * gamma[1*QKD + j + 64] + beta[1*QKD + j + 64];
        g_linq_bf[(size_t)tok * QKD + j]      = __float2bfloat16(a1 * cs - a2 * sn);
        g_linq_bf[(size_t)tok * QKD + j + 64] = __float2bfloat16(a2 * cs + a1 * sn);
    }
    {
        float a1 = v1 * gamma[3*QKD + j]      + beta[3*QKD + j];
        float a2 = v2 * gamma[3*QKD + j + 64] + beta[3*QKD + j + 64];
        __nv_bfloat16* base = g_linkT_bf + (size_t)b * QKD * SEQ;
        base[(size_t)j * SEQ + n]        = __float2bfloat16(a1 * cs - a2 * sn);
        base[(size_t)(j + 64) * SEQ + n] = __float2bfloat16(a2 * cs + a1 * sn);
    }
}

// ---------------------------------------------------------------------------
extern "C" void kernel_launch(void* const* d_in, const int* in_sizes, int n_in,
                              void* d_out, int out_size) {
    const float* x        = (const float*)d_in[0];
    const float* ln_g     = (const float*)d_in[1];
    const float* ln_b     = (const float*)d_in[2];
    const float* W_hidden = (const float*)d_in[3];
    const float* b_hidden = (const float*)d_in[4];
    const float* W_qk     = (const float*)d_in[5];
    const float* b_qk     = (const float*)d_in[6];
    const float* os_gamma = (const float*)d_in[7];
    const float* os_beta  = (const float*)d_in[8];
    const float* W_out    = (const float*)d_in[9];
    const float* b_out    = (const float*)d_in[10];
    float* out = (float*)d_out;

    __nv_bfloat16 *normed_bf, *whT, *wqkT, *woT, *gated_bf, *h_bf;
    float *qk;
    cudaGetSymbolAddress((void**)&normed_bf, g_normed_bf);
    cudaGetSymbolAddress((void**)&whT,  g_whT);
    cudaGetSymbolAddress((void**)&wqkT, g_wqkT);
    cudaGetSymbolAddress((void**)&woT,  g_woT);
    cudaGetSymbolAddress((void**)&gated_bf, g_gated_bf);
    cudaGetSymbolAddress((void**)&h_bf, g_h_bf);
    cudaGetSymbolAddress((void**)&qk, g_qk);

    const int SMEM_BIG   = 4 * (16384 + 32768);   // 196608 (N_CTA=256)
    const int SMEM_SMALL = 4 * (16384 + 16384);   // 131072 (N_CTA=128)
    const int SMEM_ATTN  = 4 * 128 * 128;         // 64 KB
    const int SMEM_LK    = 2 * 16384 + 2 * 8192;  // 48 KB
    cudaFuncSetAttribute(mm_bf16_kernel<256,1024,true,false,true>,
                         cudaFuncAttributeMaxDynamicSharedMemorySize, SMEM_BIG);
    cudaFuncSetAttribute(mm_bf16_kernel<128,1024,true,false,false>,
                         cudaFuncAttributeMaxDynamicSharedMemorySize, SMEM_SMALL);
    cudaFuncSetAttribute(mm_bf16_kernel<256,2048,false,true,false>,
                         cudaFuncAttributeMaxDynamicSharedMemorySize, SMEM_BIG);
    cudaFuncSetAttribute(attn_hmma_kernel,
                         cudaFuncAttributeMaxDynamicSharedMemorySize, SMEM_ATTN);
    cudaFuncSetAttribute(linkv_hmma_kernel,
                         cudaFuncAttributeMaxDynamicSharedMemorySize, SMEM_LK);
    cudaFuncSetAttribute(fused_hmma_kernel,
                         cudaFuncAttributeMaxDynamicSharedMemorySize, SMEM_ATTN);

    transpose_bf_kernel<<<dim3(TWOH/32, DD/32), dim3(32,8)>>>(W_hidden, whT, DD, TWOH);
    transpose_bf_kernel<<<dim3(QKD/32,  DD/32), dim3(32,8)>>>(W_qk,  wqkT, DD, QKD);
    transpose_bf_kernel<<<dim3(DD/32, HHID/32), dim3(32,8)>>>(W_out, woT,  HHID, DD);

    rope_table_kernel<<<dim3(64, SEQ/256), 256>>>();
    ln_kernel<<<MROWS, 256>>>(x, ln_g, ln_b);

    // h = silu(normed @ W_hidden + b) -> bf16 [8192, 4096]
    mm_bf16_kernel<256,1024,true,false,true><<<dim3(TWOH/256, MROWS/128), 256, SMEM_BIG>>>(
        normed_bf, whT, b_hidden, nullptr, nullptr, h_bf, TWOH);
    // qk = silu(normed @ W_qk + b) -> fp32 [8192, 128]
    mm_bf16_kernel<128,1024,true,false,false><<<dim3(QKD/128, MROWS/128), 256, SMEM_SMALL>>>(
        normed_bf, wqkT, b_qk, nullptr, qk, nullptr, QKD);

    rope_apply_kernel<<<MROWS/4, 256>>>(os_gamma, os_beta);
    attn_hmma_kernel<<<dim3(GG/128, GG/128, NGRP), 256, SMEM_ATTN>>>();
    linkv_hmma_kernel<<<dim3(HHID/64, BB), 256, SMEM_LK>>>();
    fused_hmma_kernel<<<dim3(HHID/128, MROWS/128), 256, SMEM_ATTN>>>();

    // out = gated @ W_out + b_out + x  [8192, 1024]
    mm_bf16_kernel<256,2048,false,true,false><<<dim3(DD/256, MROWS/128), 256, SMEM_BIG>>>(
        gated_bf, woT, b_out, x, out, nullptr, DD);
}